// round 11
// baseline (speedup 1.0000x reference)
#include <cuda_runtime.h>
#include <cuda_fp16.h>
#include <stdint.h>
#include <math.h>

// ---------------- scratch buffers (static device memory, no allocs) ----------
#define NTOK 4096              // 4 * 1024 rows
#define HID  1024
__device__ float g_X1 [NTOK * HID];
__device__ float g_F  [NTOK * HID];
__device__ float g_bqkv[3 * HID];
__device__ __half g_Ah[NTOK * HID];       // activations fp16 (x / O / X1)
__device__ __half g_Hh[NTOK * 4 * HID];   // QKV, later FF hidden
__device__ __half g_Bq[3 * HID * HID];    // W_{q,k,v}^T fp16
__device__ __half g_Bo[HID * HID];        // Wo^T
__device__ __half g_B1[4 * HID * HID];    // W1^T
__device__ __half g_B2[4 * HID * HID];    // W2^T

// ---------------- PTX helpers (arch-neutral only) -----------------------------
__device__ __forceinline__ uint32_t smem_u32(const void* p) {
    uint32_t a;
    asm("{ .reg .u64 t; cvta.to.shared.u64 t, %1; cvt.u32.u64 %0, t; }"
        : "=r"(a) : "l"(p));
    return a;
}
#define CP_ASYNC16(s, g) \
    asm volatile("cp.async.cg.shared.global [%0], [%1], 16;" :: "r"(s), "l"(g))
#define CP_COMMIT() asm volatile("cp.async.commit_group;" ::: "memory")
#define CP_WAIT(n)  asm volatile("cp.async.wait_group %0;" :: "n"(n) : "memory")
#define LDSM_X4(r, addr) \
    asm volatile("ldmatrix.sync.aligned.m8n8.x4.shared.b16 {%0,%1,%2,%3}, [%4];" \
        : "=r"((r)[0]), "=r"((r)[1]), "=r"((r)[2]), "=r"((r)[3]) : "r"(addr))
#define LDSM_X2(r, addr) \
    asm volatile("ldmatrix.sync.aligned.m8n8.x2.shared.b16 {%0,%1}, [%2];" \
        : "=r"((r)[0]), "=r"((r)[1]) : "r"(addr))
#define LDSM_X2T(r, addr) \
    asm volatile("ldmatrix.sync.aligned.m8n8.x2.trans.shared.b16 {%0,%1}, [%2];" \
        : "=r"((r)[0]), "=r"((r)[1]) : "r"(addr))
#define MMAF16(c, a, b0, b1) \
    asm volatile("mma.sync.aligned.m16n8k16.row.col.f32.f16.f16.f32 " \
        "{%0,%1,%2,%3}, {%4,%5,%6,%7}, {%8,%9}, {%0,%1,%2,%3};" \
        : "+f"((c)[0]), "+f"((c)[1]), "+f"((c)[2]), "+f"((c)[3]) \
        : "r"((a)[0]), "r"((a)[1]), "r"((a)[2]), "r"((a)[3]), "r"(b0), "r"(b1))

__device__ __forceinline__ uint32_t pack_h2f(float x, float y) {
    __half2 p = __halves2half2(__float2half_rn(x), __float2half_rn(y));
    return *reinterpret_cast<uint32_t*>(&p);
}

// ---------------- conversion kernels -----------------------------------------
// fp32 -> fp16
__global__ __launch_bounds__(256) void cvt_kernel(
    const float* __restrict__ A, __half* __restrict__ H, int n4)
{
    int i = blockIdx.x * 256 + threadIdx.x;
    if (i >= n4) return;
    float4 v = ((const float4*)A)[i];
    ((__half2*)H)[i * 2 + 0] = __halves2half2(__float2half_rn(v.x), __float2half_rn(v.y));
    ((__half2*)H)[i * 2 + 1] = __halves2half2(__float2half_rn(v.z), __float2half_rn(v.w));
}

// transpose+round one 32x32 tile of W [K x N] fp32 -> H [N x K] fp16
__device__ __forceinline__ void tsplit_tile(
    const float* __restrict__ W, __half* __restrict__ H,
    int K, int N, int bk, int bn, float (*t)[33])
{
    const int tx = threadIdx.x, ty = threadIdx.y;
    #pragma unroll
    for (int j = 0; j < 4; ++j)
        t[ty + j * 8][tx] = W[(size_t)(bk + ty + j * 8) * N + bn + tx];
    __syncthreads();
    #pragma unroll
    for (int j = 0; j < 4; ++j) {
        int r = ty + j * 8;
        H[(size_t)(bn + r) * K + bk + tx] = __float2half_rn(t[tx][r]);
    }
}

// batched QKV transpose: three [1024x1024] weights via blockIdx.z
__global__ __launch_bounds__(256) void tsplit3_kernel(
    const float* __restrict__ W0, const float* __restrict__ W1,
    const float* __restrict__ W2, __half* __restrict__ H)
{
    __shared__ float t[32][33];
    const float* W = (blockIdx.z == 0) ? W0 : (blockIdx.z == 1) ? W1 : W2;
    __half* Hd = H + (size_t)blockIdx.z * HID * HID;
    tsplit_tile(W, Hd, HID, HID, blockIdx.y * 32, blockIdx.x * 32, t);
}

// merged transpose of Wo [1024x1024], W1 [1024x4096], W2 [4096x1024]
__global__ __launch_bounds__(256) void tsplitAll_kernel(
    const float* __restrict__ Wo, const float* __restrict__ W1,
    const float* __restrict__ W2, __half* __restrict__ Ho,
    __half* __restrict__ H1, __half* __restrict__ H2)
{
    __shared__ float t[32][33];
    int id = blockIdx.x;
    if (id < 1024) {                       // Wo: K=1024, N=1024 (32x32 tiles)
        tsplit_tile(Wo, Ho, HID, HID, (id >> 5) * 32, (id & 31) * 32, t);
    } else if (id < 5120) {                // W1: K=1024, N=4096 (32 x 128)
        int i2 = id - 1024;
        tsplit_tile(W1, H1, HID, 4 * HID, (i2 >> 7) * 32, (i2 & 127) * 32, t);
    } else {                               // W2: K=4096, N=1024 (128 x 32)
        int i2 = id - 5120;
        tsplit_tile(W2, H2, 4 * HID, HID, (i2 >> 5) * 32, (i2 & 31) * 32, t);
    }
}

// ---------------- single-fp16 tensor-core GEMM (3-stage, 1 sync/k-tile) ------
// C = act(A @ B^T + bias); A [M,K] fp16, B [N,K] fp16, fp32 accum.
#define G_PART  8192
#define G_STAGE (2 * G_PART)     // 16 KB per stage
#define G_SMEM  (3 * G_STAGE)    // 48 KB ring

__global__ __launch_bounds__(256) void gemm_tc_kernel(
    const __half* __restrict__ Ah, const __half* __restrict__ Bh,
    const float* __restrict__ bias,
    float* __restrict__ Cf, __half* __restrict__ Ch,
    int M, int N, int K, int act)
{
    extern __shared__ char smem[];
    const uint32_t sb = smem_u32(smem);
    const int tid = threadIdx.x;
    const int wid = tid >> 5, lane = tid & 31;
    const int warp_m = wid >> 2, warp_n = wid & 3;
    const int bm = blockIdx.y * 128, bn = blockIdx.x * 128;

    float acc[4][4][4];
    #pragma unroll
    for (int i = 0; i < 4; ++i)
        #pragma unroll
        for (int j = 0; j < 4; ++j)
            #pragma unroll
            for (int r = 0; r < 4; ++r) acc[i][j][r] = 0.f;

    const int swz = (lane & 7) >> 1;
    const int rA = warp_m * 64 + ((lane >> 3) & 1) * 8 + (lane & 7);
    const int kA = lane >> 4;
    const int rB = warp_n * 32 + (lane >> 4) * 8 + (lane & 7);
    const int kB = (lane >> 3) & 1;

    const int nst = K >> 5;

    auto load_stage = [&](int j, int slot) {
        const uint32_t st = sb + (uint32_t)slot * G_STAGE;
        const int kc = j * 32;
        #pragma unroll
        for (int t = 0; t < 2; ++t) {
            int idx = tid + t * 256;
            int row = idx >> 2, ch = idx & 3;
            uint32_t so = (uint32_t)row * 64 + (uint32_t)((ch ^ ((row >> 1) & 3)) << 4);
            size_t ga = (size_t)(bm + row) * K + kc + ch * 8;
            size_t gb = (size_t)(bn + row) * K + kc + ch * 8;
            CP_ASYNC16(st + 0 * G_PART + so, Ah + ga);
            CP_ASYNC16(st + 1 * G_PART + so, Bh + gb);
        }
        CP_COMMIT();
    };

    load_stage(0, 0);
    load_stage(1, 1);

    int slot = 0, slot2 = 2;   // slot = j%3, slot2 = (j+2)%3
    for (int j = 0; j < nst; ++j) {
        if (j + 1 < nst) { CP_WAIT(1); }   // stage j complete
        else             { CP_WAIT(0); }
        __syncthreads();                    // everyone done with slot (j-1)%3 == slot2
        if (j + 2 < nst) load_stage(j + 2, slot2);

        const uint32_t st = sb + (uint32_t)slot * G_STAGE;
        #pragma unroll
        for (int ks = 0; ks < 2; ++ks) {
            uint32_t ah[4][4], bh[2][4];
            #pragma unroll
            for (int mt = 0; mt < 4; ++mt) {
                uint32_t ao = (uint32_t)(rA + mt * 16) * 64
                            + (uint32_t)(((ks * 2 + kA) ^ swz) << 4);
                LDSM_X4(ah[mt], st + 0 * G_PART + ao);
            }
            #pragma unroll
            for (int np = 0; np < 2; ++np) {
                uint32_t bo = (uint32_t)(rB + np * 16) * 64
                            + (uint32_t)(((ks * 2 + kB) ^ swz) << 4);
                LDSM_X4(bh[np], st + 1 * G_PART + bo);
            }
            #pragma unroll
            for (int mt = 0; mt < 4; ++mt)
                #pragma unroll
                for (int nt = 0; nt < 4; ++nt) {
                    const uint32_t* bhp = &bh[nt >> 1][(nt & 1) * 2];
                    MMAF16(acc[mt][nt], ah[mt], bhp[0], bhp[1]);
                }
        }
        slot  = (slot  == 2) ? 0 : slot  + 1;
        slot2 = (slot2 == 2) ? 0 : slot2 + 1;
    }

    // epilogue
    #pragma unroll
    for (int mt = 0; mt < 4; ++mt)
        #pragma unroll
        for (int nt = 0; nt < 4; ++nt) {
            int row0 = bm + warp_m * 64 + mt * 16 + (lane >> 2);
            int col  = bn + warp_n * 32 + nt * 8 + (lane & 3) * 2;
            float b0 = bias[col], b1 = bias[col + 1];
            float v[4];
            v[0] = acc[mt][nt][0] + b0;
            v[1] = acc[mt][nt][1] + b1;
            v[2] = acc[mt][nt][2] + b0;
            v[3] = acc[mt][nt][3] + b1;
            if (act) {
                #pragma unroll
                for (int r = 0; r < 4; ++r)
                    v[r] = 0.5f * v[r] * (1.f + erff(v[r] * 0.70710678118654752f));
            }
            if (Cf) {
                *(float2*)&Cf[(size_t)row0 * N + col]       = make_float2(v[0], v[1]);
                *(float2*)&Cf[(size_t)(row0 + 8) * N + col] = make_float2(v[2], v[3]);
            } else {
                uint32_t p0 = pack_h2f(v[0], v[1]);
                uint32_t p1 = pack_h2f(v[2], v[3]);
                *(uint32_t*)&Ch[(size_t)row0 * N + col]       = p0;
                *(uint32_t*)&Ch[(size_t)(row0 + 8) * N + col] = p1;
            }
        }
}

// ---------------- tensor-core attention (pipelined, 2 syncs/iter) -------------
// QKV packed fp16 [4096][3072]. Per block (a, n): 16 warps, warp = head.
// 3-slot KV ring (prefetch at iter top), sc double-buffered; AV(ap-1) and
// scores(ap) fused into one tensor phase.
#define SCP(hh, b, p) ((hh) * 272 + (b) * 17 + (p))
#define SCSZ 4352                    // floats per sc copy (16*272)
#define AT_STG 65536                 // K (32KB) + V (32KB) per slot
#define ATTN_SMEM (3 * AT_STG + 2 * SCSZ * 4)   // 196608 + 34816 = 231424

__global__ __launch_bounds__(512, 1) void attn_kernel(
    const __half* __restrict__ Ph, __half* __restrict__ Oh)
{
    extern __shared__ char smem[];
    const uint32_t sb = smem_u32(smem);
    float* sc0 = (float*)(smem + 3 * AT_STG);
    float* sc1 = sc0 + SCSZ;

    const int tid = threadIdx.x, lane = tid & 31, h = tid >> 5;
    const int a = blockIdx.x, n = blockIdx.y;
    const int lr = lane >> 2, lc = lane & 3;

    // ---- stage Q into slot 0, extract fragments ----
    {
        #pragma unroll
        for (int t = 0; t < 4; ++t) {
            int f = tid + t * 512;
            int hh = f >> 7, bp = (f >> 3) & 15, c = f & 7;
            uint32_t dst = (uint32_t)hh * 2048 + bp * 128 + ((c ^ (bp & 7)) << 4);
            size_t src = (size_t)(n * 1024 + hh * 64 + a) * 3072 + bp * 64 + c * 8;
            CP_ASYNC16(sb + dst, Ph + src);
        }
        CP_COMMIT(); CP_WAIT(0); __syncthreads();
    }
    uint32_t qh[4][4];
    {
        int b = lane & 15, cs = lane >> 4;
        #pragma unroll
        for (int ks = 0; ks < 4; ++ks) {
            uint32_t ad = (uint32_t)h * 2048 + b * 128
                        + (((ks * 2 + cs) ^ (b & 7)) << 4);
            LDSM_X4(qh[ks], sb + ad);
        }
    }
    __syncthreads();   // everyone done reading Q before KV overwrites slot 0

    auto stageKV = [&](int ap, int s) {
        uint32_t base = sb + (uint32_t)s * AT_STG;
        #pragma unroll
        for (int t = 0; t < 4; ++t) {
            int f = tid + t * 512;
            int hh = f >> 7, bp = (f >> 3) & 15, c = f & 7;
            uint32_t dst = (uint32_t)hh * 2048 + bp * 128 + ((c ^ (bp & 7)) << 4);
            size_t row = (size_t)(n * 1024 + hh * 64 + ap) * 3072;
            CP_ASYNC16(base + dst,         Ph + row + 1024 + bp * 64 + c * 8);
            CP_ASYNC16(base + 32768 + dst, Ph + row + 2048 + bp * 64 + c * 8);
        }
        CP_COMMIT();
    };

    float o[8][4];
    #pragma unroll
    for (int nt = 0; nt < 8; ++nt)
        #pragma unroll
        for (int r = 0; r < 4; ++r) o[nt][r] = 0.f;

    stageKV(0, 0);
    // slot(ap) = ap % 3; sc(ap) = ap & 1
    for (int ap = 0; ap <= 64; ++ap) {
        if (ap < 64) CP_WAIT(0);   // KV(ap) complete (single group in flight)
        __syncthreads();           // syncA: + softmax(ap-1) done; ring slot (ap+1)%3 dead

        // prefetch KV(ap+1) into slot (ap+1)%3 (K there read at iter ap-2,
        // V read at iter ap-1 AV phase — both fenced by earlier syncs)
        if (ap + 1 < 64) stageKV(ap + 1, (ap + 1) % 3);

        // ---- AV(ap-1): O += W V  (reads sc[(ap-1)&1], V slot (ap-1)%3) ----
        if (ap > 0) {
            float* scp = ((ap - 1) & 1) ? sc1 : sc0;
            uint32_t awh[4];
            awh[0] = pack_h2f(scp[SCP(h, lr,     2 * lc)],     scp[SCP(h, lr,     2 * lc + 1)]);
            awh[1] = pack_h2f(scp[SCP(h, lr + 8, 2 * lc)],     scp[SCP(h, lr + 8, 2 * lc + 1)]);
            awh[2] = pack_h2f(scp[SCP(h, lr,     2 * lc + 8)], scp[SCP(h, lr,     2 * lc + 9)]);
            awh[3] = pack_h2f(scp[SCP(h, lr + 8, 2 * lc + 8)], scp[SCP(h, lr + 8, 2 * lc + 9)]);
            const uint32_t vb = sb + (uint32_t)((ap - 1) % 3) * AT_STG + 32768;
            int bp = lane & 15;
            #pragma unroll
            for (int nt = 0; nt < 8; ++nt) {
                uint32_t ad = (uint32_t)h * 2048 + bp * 128 + ((nt ^ (bp & 7)) << 4);
                uint32_t v2[2];
                LDSM_X2T(v2, vb + ad);
                MMAF16(o[nt], awh, v2[0], v2[1]);
            }
        }

        // ---- scores(ap): S = Q K^T  (K slot ap%3 -> sc[ap&1] raw) ----
        if (ap < 64) {
            const uint32_t kb = sb + (uint32_t)(ap % 3) * AT_STG;
            float* scw = (ap & 1) ? sc1 : sc0;
            float sv[2][4];
            #pragma unroll
            for (int nt = 0; nt < 2; ++nt)
                #pragma unroll
                for (int r = 0; r < 4; ++r) sv[nt][r] = 0.f;
            int bpr = lane & 7, khalf = (lane >> 3) & 1;
            #pragma unroll
            for (int ks = 0; ks < 4; ++ks)
                #pragma unroll
                for (int nt = 0; nt < 2; ++nt) {
                    int row = nt * 8 + bpr;
                    uint32_t ad = (uint32_t)h * 2048 + row * 128
                                + (((ks * 2 + khalf) ^ (row & 7)) << 4);
                    uint32_t k2[2];
                    LDSM_X2(k2, kb + ad);
                    MMAF16(sv[nt], qh[ks], k2[0], k2[1]);
                }
            #pragma unroll
            for (int nt = 0; nt < 2; ++nt) {
                int c0 = nt * 8 + 2 * lc;
                scw[SCP(h, lr,     c0)]     = sv[nt][0] * 0.03125f;
                scw[SCP(h, lr,     c0 + 1)] = sv[nt][1] * 0.03125f;
                scw[SCP(h, lr + 8, c0)]     = sv[nt][2] * 0.03125f;
                scw[SCP(h, lr + 8, c0 + 1)] = sv[nt][3] * 0.03125f;
            }
        }
        __syncthreads();   // syncB: sc(ap) written; V(ap-1) & K(ap) reads done

        // ---- head-softmax(ap): thread p owns (b = p>>4, b' = p&15) ----
        if (ap < 64 && tid < 256) {
            float* scw = (ap & 1) ? sc1 : sc0;
            const int pb = tid >> 4, pbp = tid & 15;
            float m = -1e30f;
            #pragma unroll
            for (int hh = 0; hh < 16; ++hh) m = fmaxf(m, scw[SCP(hh, pb, pbp)]);
            float ssum = 0.f;
            #pragma unroll
            for (int hh = 0; hh < 16; ++hh) {
                float e = __expf(scw[SCP(hh, pb, pbp)] - m);
                ssum += e;
                scw[SCP(hh, pb, pbp)] = e;
            }
            float inv = 1.f / ssum;
            #pragma unroll
            for (int hh = 0; hh < 16; ++hh) scw[SCP(hh, pb, pbp)] *= inv;
        }
        // next iter's syncA fences softmax before AV reads it
    }

    // ---- write O (one 1024-col row per head) as fp16 ----
    const size_t orow = (size_t)(n * 1024 + h * 64 + a) * 1024;
    #pragma unroll
    for (int nt = 0; nt < 8; ++nt) {
        int c0 = nt * 8 + 2 * lc;
        uint32_t p0 = pack_h2f(o[nt][0], o[nt][1]);
        uint32_t p1 = pack_h2f(o[nt][2], o[nt][3]);
        *(uint32_t*)(Oh + orow + lr * 64 + c0)       = p0;
        *(uint32_t*)(Oh + orow + (lr + 8) * 64 + c0) = p1;
    }
}

// ---------------- fused residual + LayerNorm (+ optional fp16 emit) ----------
__global__ __launch_bounds__(256) void ln_kernel(
    const float* __restrict__ A, const float* __restrict__ R,
    const float* __restrict__ g, const float* __restrict__ bta,
    float* __restrict__ out, __half* __restrict__ Xh)
{
    __shared__ float red[16];
    const int row = blockIdx.x;
    const int tid = threadIdx.x;

    float4 v = ((const float4*)(A + (size_t)row * 1024))[tid];
    float4 r = ((const float4*)(R + (size_t)row * 1024))[tid];
    v.x += r.x; v.y += r.y; v.z += r.z; v.w += r.w;

    float s  = v.x + v.y + v.z + v.w;
    float sq = v.x * v.x + v.y * v.y + v.z * v.z + v.w * v.w;
    #pragma unroll
    for (int o = 16; o > 0; o >>= 1) {
        s  += __shfl_xor_sync(0xffffffffu, s,  o);
        sq += __shfl_xor_sync(0xffffffffu, sq, o);
    }
    if ((tid & 31) == 0) { red[tid >> 5] = s; red[8 + (tid >> 5)] = sq; }
    __syncthreads();
    float S = 0.f, SQ = 0.f;
    #pragma unroll
    for (int w = 0; w < 8; ++w) { S += red[w]; SQ += red[8 + w]; }

    const float mean = S * (1.f / 1024.f);
    const float var  = SQ * (1.f / 1024.f) - mean * mean;
    const float rstd = rsqrtf(var + 1e-5f);

    float4 gv = ((const float4*)g)[tid];
    float4 bv = ((const float4*)bta)[tid];
    float4 o;
    o.x = (v.x - mean) * rstd * gv.x + bv.x;
    o.y = (v.y - mean) * rstd * gv.y + bv.y;
    o.z = (v.z - mean) * rstd * gv.z + bv.z;
    o.w = (v.w - mean) * rstd * gv.w + bv.w;
    ((float4*)(out + (size_t)row * 1024))[tid] = o;

    if (Xh) {
        size_t oo = (size_t)row * 1024 + tid * 4;
        *(__half2*)(Xh + oo)     = __halves2half2(__float2half_rn(o.x), __float2half_rn(o.y));
        *(__half2*)(Xh + oo + 2) = __halves2half2(__float2half_rn(o.z), __float2half_rn(o.w));
    }
}

// ---------------- launch ------------------------------------------------------
extern "C" void kernel_launch(void* const* d_in, const int* in_sizes, int n_in,
                              void* d_out, int out_size)
{
    const float* x  = (const float*)d_in[0];
    const float* Wq = (const float*)d_in[1];
    const float* bq = (const float*)d_in[2];
    const float* Wk = (const float*)d_in[3];
    const float* bk = (const float*)d_in[4];
    const float* Wv = (const float*)d_in[5];
    const float* bv = (const float*)d_in[6];
    const float* Wo = (const float*)d_in[7];
    const float* bo = (const float*)d_in[8];
    const float* g1 = (const float*)d_in[9];
    const float* b1 = (const float*)d_in[10];
    const float* W1 = (const float*)d_in[11];
    const float* c1 = (const float*)d_in[12];
    const float* W2 = (const float*)d_in[13];
    const float* c2 = (const float*)d_in[14];
    const float* g2 = (const float*)d_in[15];
    const float* b2 = (const float*)d_in[16];
    float* out = (float*)d_out;

    float *pX1, *pF, *pbqkv;
    __half *pAh, *pHh, *pBq, *pBo, *pB1, *pB2;
    cudaGetSymbolAddress((void**)&pX1,  g_X1);
    cudaGetSymbolAddress((void**)&pF,   g_F);
    cudaGetSymbolAddress((void**)&pbqkv,g_bqkv);
    cudaGetSymbolAddress((void**)&pAh,  g_Ah);
    cudaGetSymbolAddress((void**)&pHh,  g_Hh);
    cudaGetSymbolAddress((void**)&pBq,  g_Bq);
    cudaGetSymbolAddress((void**)&pBo,  g_Bo);
    cudaGetSymbolAddress((void**)&pB1,  g_B1);
    cudaGetSymbolAddress((void**)&pB2,  g_B2);

    cudaFuncSetAttribute(attn_kernel, cudaFuncAttributeMaxDynamicSharedMemorySize, ATTN_SMEM);
    cudaFuncSetAttribute(gemm_tc_kernel, cudaFuncAttributeMaxDynamicSharedMemorySize, G_SMEM);

    dim3 blk(256);
    dim3 t32(32, 8);
    const int n4_1 = NTOK * HID / 4;
    dim3 gs1((n4_1 + 255) / 256);
    dim3 tg3(HID / 32, HID / 32, 3);
    dim3 ggqkv(3 * HID / 128, NTOK / 128);
    dim3 gg1(HID / 128, NTOK / 128);
    dim3 gg4(4 * HID / 128, NTOK / 128);

    // ---- conversions: x, W_{q,k,v}^T, and all remaining weights up front ----
    cvt_kernel<<<gs1, blk>>>(x, pAh, n4_1);
    tsplit3_kernel<<<tg3, t32>>>(Wq, Wk, Wv, pBq);
    tsplitAll_kernel<<<9216, t32>>>(Wo, W1, W2, pBo, pB1, pB2);
    cudaMemcpyAsync(pbqkv,        bq, HID * 4, cudaMemcpyDeviceToDevice, 0);
    cudaMemcpyAsync(pbqkv + 1024, bk, HID * 4, cudaMemcpyDeviceToDevice, 0);
    cudaMemcpyAsync(pbqkv + 2048, bv, HID * 4, cudaMemcpyDeviceToDevice, 0);

    // ---- QKV GEMM (N=3072) -> fp16 ----
    gemm_tc_kernel<<<ggqkv, blk, G_SMEM>>>(pAh, pBq, pbqkv,
                                           nullptr, pHh,
                                           NTOK, 3 * HID, HID, 0);

    // ---- tensor-core attention; emits O fp16 ----
    attn_kernel<<<dim3(64, 4), 512, ATTN_SMEM>>>(pHh, pAh);

    // ---- output projection, residual + LN1 (emits X1 fp32 + fp16) ----
    gemm_tc_kernel<<<gg1, blk, G_SMEM>>>(pAh, pBo, bo,
                                         pF, nullptr,
                                         NTOK, HID, HID, 0);
    ln_kernel<<<NTOK, blk>>>(pF, x, g1, b1, pX1, pAh);

    // ---- FFN ----
    gemm_tc_kernel<<<gg4, blk, G_SMEM>>>(pAh, pB1, c1,
                                         nullptr, pHh,
                                         NTOK, 4 * HID, HID, 1);
    gemm_tc_kernel<<<gg1, blk, G_SMEM>>>(pHh, pB2, c2,
                                         pF, nullptr,
                                         NTOK, HID, 4 * HID, 0);

    // ---- residual + LN2 -> output ----
    ln_kernel<<<NTOK, blk>>>(pF, pX1, g2, b2, out, nullptr);
}

// round 12
// speedup vs baseline: 1.0152x; 1.0152x over previous
#include <cuda_runtime.h>
#include <cuda_fp16.h>
#include <stdint.h>
#include <math.h>

// ---------------- scratch buffers (static device memory, no allocs) ----------
#define NTOK 4096              // 4 * 1024 rows
#define HID  1024
__device__ float g_X1 [NTOK * HID];
__device__ float g_F  [NTOK * HID];
__device__ float g_bqkv[3 * HID];
__device__ __half g_Ah[NTOK * HID];       // activations fp16 (x / O / X1)
__device__ __half g_Hh[NTOK * 4 * HID];   // QKV, later FF hidden
__device__ __half g_Bq[3 * HID * HID];    // W_{q,k,v}^T fp16
__device__ __half g_Bo[HID * HID];        // Wo^T
__device__ __half g_B1[4 * HID * HID];    // W1^T
__device__ __half g_B2[4 * HID * HID];    // W2^T

// ---------------- PTX helpers (arch-neutral only) -----------------------------
__device__ __forceinline__ uint32_t smem_u32(const void* p) {
    uint32_t a;
    asm("{ .reg .u64 t; cvta.to.shared.u64 t, %1; cvt.u32.u64 %0, t; }"
        : "=r"(a) : "l"(p));
    return a;
}
#define CP_ASYNC16(s, g) \
    asm volatile("cp.async.cg.shared.global [%0], [%1], 16;" :: "r"(s), "l"(g))
#define CP_COMMIT() asm volatile("cp.async.commit_group;" ::: "memory")
#define CP_WAIT(n)  asm volatile("cp.async.wait_group %0;" :: "n"(n) : "memory")
#define LDSM_X4(r, addr) \
    asm volatile("ldmatrix.sync.aligned.m8n8.x4.shared.b16 {%0,%1,%2,%3}, [%4];" \
        : "=r"((r)[0]), "=r"((r)[1]), "=r"((r)[2]), "=r"((r)[3]) : "r"(addr))
#define LDSM_X2(r, addr) \
    asm volatile("ldmatrix.sync.aligned.m8n8.x2.shared.b16 {%0,%1}, [%2];" \
        : "=r"((r)[0]), "=r"((r)[1]) : "r"(addr))
#define LDSM_X2T(r, addr) \
    asm volatile("ldmatrix.sync.aligned.m8n8.x2.trans.shared.b16 {%0,%1}, [%2];" \
        : "=r"((r)[0]), "=r"((r)[1]) : "r"(addr))
#define MMAF16(c, a, b0, b1) \
    asm volatile("mma.sync.aligned.m16n8k16.row.col.f32.f16.f16.f32 " \
        "{%0,%1,%2,%3}, {%4,%5,%6,%7}, {%8,%9}, {%0,%1,%2,%3};" \
        : "+f"((c)[0]), "+f"((c)[1]), "+f"((c)[2]), "+f"((c)[3]) \
        : "r"((a)[0]), "r"((a)[1]), "r"((a)[2]), "r"((a)[3]), "r"(b0), "r"(b1))

__device__ __forceinline__ uint32_t pack_h2f(float x, float y) {
    __half2 p = __halves2half2(__float2half_rn(x), __float2half_rn(y));
    return *reinterpret_cast<uint32_t*>(&p);
}

// ---------------- conversion kernels -----------------------------------------
// fp32 -> fp16
__global__ __launch_bounds__(256) void cvt_kernel(
    const float* __restrict__ A, __half* __restrict__ H, int n4)
{
    int i = blockIdx.x * 256 + threadIdx.x;
    if (i >= n4) return;
    float4 v = ((const float4*)A)[i];
    ((__half2*)H)[i * 2 + 0] = __halves2half2(__float2half_rn(v.x), __float2half_rn(v.y));
    ((__half2*)H)[i * 2 + 1] = __halves2half2(__float2half_rn(v.z), __float2half_rn(v.w));
}

// transpose+round one 32x32 tile of W [K x N] fp32 -> H [N x K] fp16
__device__ __forceinline__ void tsplit_tile(
    const float* __restrict__ W, __half* __restrict__ H,
    int K, int N, int bk, int bn, float (*t)[33])
{
    const int tx = threadIdx.x, ty = threadIdx.y;
    #pragma unroll
    for (int j = 0; j < 4; ++j)
        t[ty + j * 8][tx] = W[(size_t)(bk + ty + j * 8) * N + bn + tx];
    __syncthreads();
    #pragma unroll
    for (int j = 0; j < 4; ++j) {
        int r = ty + j * 8;
        H[(size_t)(bn + r) * K + bk + tx] = __float2half_rn(t[tx][r]);
    }
}

// one launch: all weight transposes + QKV bias packing
__global__ __launch_bounds__(256) void prep_kernel(
    const float* __restrict__ Wq, const float* __restrict__ Wk,
    const float* __restrict__ Wv, const float* __restrict__ Wo,
    const float* __restrict__ W1, const float* __restrict__ W2,
    const float* __restrict__ bq, const float* __restrict__ bk,
    const float* __restrict__ bv,
    __half* __restrict__ Hq, __half* __restrict__ Ho,
    __half* __restrict__ H1, __half* __restrict__ H2,
    float* __restrict__ bqkv)
{
    __shared__ float t[32][33];
    int id = blockIdx.x;
    if (id < 3072) {                        // Wq|Wk|Wv: 3 x 1024 tiles
        int z = id >> 10, i2 = id & 1023;
        const float* W = (z == 0) ? Wq : (z == 1) ? Wk : Wv;
        tsplit_tile(W, Hq + (size_t)z * HID * HID, HID, HID,
                    (i2 >> 5) * 32, (i2 & 31) * 32, t);
    } else if (id < 4096) {                 // Wo
        int i2 = id - 3072;
        tsplit_tile(Wo, Ho, HID, HID, (i2 >> 5) * 32, (i2 & 31) * 32, t);
    } else if (id < 8192) {                 // W1: K=1024, N=4096
        int i2 = id - 4096;
        tsplit_tile(W1, H1, HID, 4 * HID, (i2 >> 7) * 32, (i2 & 127) * 32, t);
    } else if (id < 12288) {                // W2: K=4096, N=1024
        int i2 = id - 8192;
        tsplit_tile(W2, H2, 4 * HID, HID, (i2 >> 5) * 32, (i2 & 31) * 32, t);
    } else {                                // bias pack: ids 12288..12290
        int z = id - 12288;
        const float* b = (z == 0) ? bq : (z == 1) ? bk : bv;
        int tid = threadIdx.y * 32 + threadIdx.x;
        #pragma unroll
        for (int j = 0; j < 4; ++j)
            bqkv[z * 1024 + tid + j * 256] = b[tid + j * 256];
    }
}

// ---------------- single-fp16 tensor-core GEMM (3-stage, 1 sync/k-tile) ------
// C = act(A @ B^T + bias); A [M,K] fp16, B [N,K] fp16, fp32 accum.
#define G_PART  8192
#define G_STAGE (2 * G_PART)     // 16 KB per stage
#define G_SMEM  (3 * G_STAGE)    // 48 KB ring

__global__ __launch_bounds__(256) void gemm_tc_kernel(
    const __half* __restrict__ Ah, const __half* __restrict__ Bh,
    const float* __restrict__ bias,
    float* __restrict__ Cf, __half* __restrict__ Ch,
    int M, int N, int K, int act)
{
    extern __shared__ char smem[];
    const uint32_t sb = smem_u32(smem);
    const int tid = threadIdx.x;
    const int wid = tid >> 5, lane = tid & 31;
    const int warp_m = wid >> 2, warp_n = wid & 3;
    const int bm = blockIdx.y * 128, bn = blockIdx.x * 128;

    float acc[4][4][4];
    #pragma unroll
    for (int i = 0; i < 4; ++i)
        #pragma unroll
        for (int j = 0; j < 4; ++j)
            #pragma unroll
            for (int r = 0; r < 4; ++r) acc[i][j][r] = 0.f;

    const int swz = (lane & 7) >> 1;
    const int rA = warp_m * 64 + ((lane >> 3) & 1) * 8 + (lane & 7);
    const int kA = lane >> 4;
    const int rB = warp_n * 32 + (lane >> 4) * 8 + (lane & 7);
    const int kB = (lane >> 3) & 1;

    const int nst = K >> 5;

    auto load_stage = [&](int j, int slot) {
        const uint32_t st = sb + (uint32_t)slot * G_STAGE;
        const int kc = j * 32;
        #pragma unroll
        for (int t = 0; t < 2; ++t) {
            int idx = tid + t * 256;
            int row = idx >> 2, ch = idx & 3;
            uint32_t so = (uint32_t)row * 64 + (uint32_t)((ch ^ ((row >> 1) & 3)) << 4);
            size_t ga = (size_t)(bm + row) * K + kc + ch * 8;
            size_t gb = (size_t)(bn + row) * K + kc + ch * 8;
            CP_ASYNC16(st + 0 * G_PART + so, Ah + ga);
            CP_ASYNC16(st + 1 * G_PART + so, Bh + gb);
        }
        CP_COMMIT();
    };

    load_stage(0, 0);
    load_stage(1, 1);

    int slot = 0, slot2 = 2;   // slot = j%3, slot2 = (j+2)%3
    for (int j = 0; j < nst; ++j) {
        if (j + 1 < nst) { CP_WAIT(1); }   // stage j complete
        else             { CP_WAIT(0); }
        __syncthreads();                    // everyone done with slot (j-1)%3 == slot2
        if (j + 2 < nst) load_stage(j + 2, slot2);

        const uint32_t st = sb + (uint32_t)slot * G_STAGE;
        #pragma unroll
        for (int ks = 0; ks < 2; ++ks) {
            uint32_t ah[4][4], bh[2][4];
            #pragma unroll
            for (int mt = 0; mt < 4; ++mt) {
                uint32_t ao = (uint32_t)(rA + mt * 16) * 64
                            + (uint32_t)(((ks * 2 + kA) ^ swz) << 4);
                LDSM_X4(ah[mt], st + 0 * G_PART + ao);
            }
            #pragma unroll
            for (int np = 0; np < 2; ++np) {
                uint32_t bo = (uint32_t)(rB + np * 16) * 64
                            + (uint32_t)(((ks * 2 + kB) ^ swz) << 4);
                LDSM_X4(bh[np], st + 1 * G_PART + bo);
            }
            #pragma unroll
            for (int mt = 0; mt < 4; ++mt)
                #pragma unroll
                for (int nt = 0; nt < 4; ++nt) {
                    const uint32_t* bhp = &bh[nt >> 1][(nt & 1) * 2];
                    MMAF16(acc[mt][nt], ah[mt], bhp[0], bhp[1]);
                }
        }
        slot  = (slot  == 2) ? 0 : slot  + 1;
        slot2 = (slot2 == 2) ? 0 : slot2 + 1;
    }

    // epilogue
    #pragma unroll
    for (int mt = 0; mt < 4; ++mt)
        #pragma unroll
        for (int nt = 0; nt < 4; ++nt) {
            int row0 = bm + warp_m * 64 + mt * 16 + (lane >> 2);
            int col  = bn + warp_n * 32 + nt * 8 + (lane & 3) * 2;
            float b0 = bias[col], b1 = bias[col + 1];
            float v[4];
            v[0] = acc[mt][nt][0] + b0;
            v[1] = acc[mt][nt][1] + b1;
            v[2] = acc[mt][nt][2] + b0;
            v[3] = acc[mt][nt][3] + b1;
            if (act) {
                #pragma unroll
                for (int r = 0; r < 4; ++r)
                    v[r] = 0.5f * v[r] * (1.f + erff(v[r] * 0.70710678118654752f));
            }
            if (Cf) {
                *(float2*)&Cf[(size_t)row0 * N + col]       = make_float2(v[0], v[1]);
                *(float2*)&Cf[(size_t)(row0 + 8) * N + col] = make_float2(v[2], v[3]);
            } else {
                uint32_t p0 = pack_h2f(v[0], v[1]);
                uint32_t p1 = pack_h2f(v[2], v[3]);
                *(uint32_t*)&Ch[(size_t)row0 * N + col]       = p0;
                *(uint32_t*)&Ch[(size_t)(row0 + 8) * N + col] = p1;
            }
        }
}

// ---------------- tensor-core attention (warp-local staging, 2 syncs/iter) ----
// QKV packed fp16 [4096][3072]. Per block (a, n): 16 warps, warp = head.
// Each warp cp.asyncs its OWN head's K/V tile (4 KB) -> no CTA barrier for
// staging; slot reuse is same-warp program-order. 3-slot ring, depth-2 prefetch.
#define SCP(hh, b, p) ((hh) * 272 + (b) * 17 + (p))
#define SCSZ 4352                    // floats (16*272)
#define AT_SLOT 65536                // per slot: 16 heads x (K 2KB + V 2KB)
#define ATTN_SMEM (3 * AT_SLOT + SCSZ * 4)   // 196608 + 17408 = 214016

__global__ __launch_bounds__(512, 1) void attn_kernel(
    const __half* __restrict__ Ph, __half* __restrict__ Oh)
{
    extern __shared__ char smem[];
    const uint32_t sb = smem_u32(smem);
    float* sc = (float*)(smem + 3 * AT_SLOT);

    const int tid = threadIdx.x, lane = tid & 31, h = tid >> 5;
    const int a = blockIdx.x, n = blockIdx.y;
    const int lr = lane >> 2, lc = lane & 3;

    // ---- stage Q (warp-local) into own region of slot 0, extract fragments --
    uint32_t qh[4][4];
    {
        const uint32_t base = sb + (uint32_t)h * 4096;
        const size_t row = (size_t)(n * 1024 + h * 64 + a) * 3072;
        #pragma unroll
        for (int t = 0; t < 4; ++t) {
            int idx = lane + t * 32;           // 0..127 chunks
            int bp = idx >> 3, c = idx & 7;
            uint32_t dst = (uint32_t)bp * 128 + ((c ^ (bp & 7)) << 4);
            CP_ASYNC16(base + dst, Ph + row + bp * 64 + c * 8);
        }
        CP_COMMIT(); CP_WAIT(0); __syncwarp();
        int b = lane & 15, cs = lane >> 4;
        #pragma unroll
        for (int ks = 0; ks < 4; ++ks) {
            uint32_t ad = base + (uint32_t)b * 128
                        + (((ks * 2 + cs) ^ (b & 7)) << 4);
            LDSM_X4(qh[ks], ad);
        }
        // ldmatrix is warp-collective; all lanes' reads complete before any
        // lane's subsequent cp.async overwrites this region.
    }

    // warp-local K/V staging for iteration ap into ring slot s
    auto stageKV = [&](int ap, int s) {
        const uint32_t base = sb + (uint32_t)s * AT_SLOT + (uint32_t)h * 4096;
        const size_t row = (size_t)(n * 1024 + h * 64 + ap) * 3072;
        #pragma unroll
        for (int t = 0; t < 4; ++t) {
            int idx = lane + t * 32;
            int bp = idx >> 3, c = idx & 7;
            uint32_t dst = (uint32_t)bp * 128 + ((c ^ (bp & 7)) << 4);
            CP_ASYNC16(base + dst,        Ph + row + 1024 + bp * 64 + c * 8);
            CP_ASYNC16(base + 2048 + dst, Ph + row + 2048 + bp * 64 + c * 8);
        }
        CP_COMMIT();
    };

    float o[8][4];
    #pragma unroll
    for (int nt = 0; nt < 8; ++nt)
        #pragma unroll
        for (int r = 0; r < 4; ++r) o[nt][r] = 0.f;

    stageKV(0, 0);
    stageKV(1, 1);

    for (int ap = 0; ap < 64; ++ap) {
        const int s = ap % 3;
        if (ap < 63) { CP_WAIT(1); }   // KV(ap) landed; KV(ap+1) may fly
        else         { CP_WAIT(0); }
        __syncwarp();

        const uint32_t kb = sb + (uint32_t)s * AT_SLOT + (uint32_t)h * 4096;
        const uint32_t vb = kb + 2048;

        // ---- scores: S = Q K^T (warp-local K) ----
        float sv[2][4];
        #pragma unroll
        for (int nt = 0; nt < 2; ++nt)
            #pragma unroll
            for (int r = 0; r < 4; ++r) sv[nt][r] = 0.f;
        {
            int bpr = lane & 7, khalf = (lane >> 3) & 1;
            #pragma unroll
            for (int ks = 0; ks < 4; ++ks)
                #pragma unroll
                for (int nt = 0; nt < 2; ++nt) {
                    int row = nt * 8 + bpr;
                    uint32_t ad = kb + (uint32_t)row * 128
                                + (((ks * 2 + khalf) ^ (row & 7)) << 4);
                    uint32_t k2[2];
                    LDSM_X2(k2, ad);
                    MMAF16(sv[nt], qh[ks], k2[0], k2[1]);
                }
        }
        #pragma unroll
        for (int nt = 0; nt < 2; ++nt) {
            int c0 = nt * 8 + 2 * lc;
            sc[SCP(h, lr,     c0)]     = sv[nt][0] * 0.03125f;
            sc[SCP(h, lr,     c0 + 1)] = sv[nt][1] * 0.03125f;
            sc[SCP(h, lr + 8, c0)]     = sv[nt][2] * 0.03125f;
            sc[SCP(h, lr + 8, c0 + 1)] = sv[nt][3] * 0.03125f;
        }
        __syncthreads();   // syncB: all heads' scores in sc

        // ---- head-softmax: thread p owns (b = p>>4, b' = p&15) ----
        if (tid < 256) {
            const int pb = tid >> 4, pbp = tid & 15;
            float m = -1e30f;
            #pragma unroll
            for (int hh = 0; hh < 16; ++hh) m = fmaxf(m, sc[SCP(hh, pb, pbp)]);
            float ssum = 0.f;
            #pragma unroll
            for (int hh = 0; hh < 16; ++hh) {
                float e = __expf(sc[SCP(hh, pb, pbp)] - m);
                ssum += e;
                sc[SCP(hh, pb, pbp)] = e;
            }
            float inv = 1.f / ssum;
            #pragma unroll
            for (int hh = 0; hh < 16; ++hh) sc[SCP(hh, pb, pbp)] *= inv;
        }
        __syncthreads();   // syncC: softmax done

        // ---- AV: O += W V (warp-local V via ldmatrix.trans) ----
        {
            uint32_t awh[4];
            awh[0] = pack_h2f(sc[SCP(h, lr,     2 * lc)],     sc[SCP(h, lr,     2 * lc + 1)]);
            awh[1] = pack_h2f(sc[SCP(h, lr + 8, 2 * lc)],     sc[SCP(h, lr + 8, 2 * lc + 1)]);
            awh[2] = pack_h2f(sc[SCP(h, lr,     2 * lc + 8)], sc[SCP(h, lr,     2 * lc + 9)]);
            awh[3] = pack_h2f(sc[SCP(h, lr + 8, 2 * lc + 8)], sc[SCP(h, lr + 8, 2 * lc + 9)]);
            int bp = lane & 15;
            #pragma unroll
            for (int nt = 0; nt < 8; ++nt) {
                uint32_t ad = vb + (uint32_t)bp * 128 + ((nt ^ (bp & 7)) << 4);
                uint32_t v2[2];
                LDSM_X2T(v2, ad);
                MMAF16(o[nt], awh, v2[0], v2[1]);
            }
        }

        // prefetch KV(ap+2) into slot (ap+2)%3 — that slot's K/V were last
        // read by THIS warp at iters ap-1 (program order; no barrier needed)
        if (ap + 2 < 64) stageKV(ap + 2, (ap + 2) % 3);
        // next iter: warp h writes sc region h only after its own AV read it,
        // and other warps' reads of region h (softmax) are fenced by syncC.
    }

    // ---- write O (one 1024-col row per head) as fp16 ----
    const size_t orow = (size_t)(n * 1024 + h * 64 + a) * 1024;
    #pragma unroll
    for (int nt = 0; nt < 8; ++nt) {
        int c0 = nt * 8 + 2 * lc;
        uint32_t p0 = pack_h2f(o[nt][0], o[nt][1]);
        uint32_t p1 = pack_h2f(o[nt][2], o[nt][3]);
        *(uint32_t*)(Oh + orow + lr * 64 + c0)       = p0;
        *(uint32_t*)(Oh + orow + (lr + 8) * 64 + c0) = p1;
    }
}

// ---------------- fused residual + LayerNorm (+ optional fp16 emit) ----------
__global__ __launch_bounds__(256) void ln_kernel(
    const float* __restrict__ A, const float* __restrict__ R,
    const float* __restrict__ g, const float* __restrict__ bta,
    float* __restrict__ out, __half* __restrict__ Xh)
{
    __shared__ float red[16];
    const int row = blockIdx.x;
    const int tid = threadIdx.x;

    float4 v = ((const float4*)(A + (size_t)row * 1024))[tid];
    float4 r = ((const float4*)(R + (size_t)row * 1024))[tid];
    v.x += r.x; v.y += r.y; v.z += r.z; v.w += r.w;

    float s  = v.x + v.y + v.z + v.w;
    float sq = v.x * v.x + v.y * v.y + v.z * v.z + v.w * v.w;
    #pragma unroll
    for (int o = 16; o > 0; o >>= 1) {
        s  += __shfl_xor_sync(0xffffffffu, s,  o);
        sq += __shfl_xor_sync(0xffffffffu, sq, o);
    }
    if ((tid & 31) == 0) { red[tid >> 5] = s; red[8 + (tid >> 5)] = sq; }
    __syncthreads();
    float S = 0.f, SQ = 0.f;
    #pragma unroll
    for (int w = 0; w < 8; ++w) { S += red[w]; SQ += red[8 + w]; }

    const float mean = S * (1.f / 1024.f);
    const float var  = SQ * (1.f / 1024.f) - mean * mean;
    const float rstd = rsqrtf(var + 1e-5f);

    float4 gv = ((const float4*)g)[tid];
    float4 bv = ((const float4*)bta)[tid];
    float4 o;
    o.x = (v.x - mean) * rstd * gv.x + bv.x;
    o.y = (v.y - mean) * rstd * gv.y + bv.y;
    o.z = (v.z - mean) * rstd * gv.z + bv.z;
    o.w = (v.w - mean) * rstd * gv.w + bv.w;
    ((float4*)(out + (size_t)row * 1024))[tid] = o;

    if (Xh) {
        size_t oo = (size_t)row * 1024 + tid * 4;
        *(__half2*)(Xh + oo)     = __halves2half2(__float2half_rn(o.x), __float2half_rn(o.y));
        *(__half2*)(Xh + oo + 2) = __halves2half2(__float2half_rn(o.z), __float2half_rn(o.w));
    }
}

// ---------------- launch ------------------------------------------------------
extern "C" void kernel_launch(void* const* d_in, const int* in_sizes, int n_in,
                              void* d_out, int out_size)
{
    const float* x  = (const float*)d_in[0];
    const float* Wq = (const float*)d_in[1];
    const float* bq = (const float*)d_in[2];
    const float* Wk = (const float*)d_in[3];
    const float* bk = (const float*)d_in[4];
    const float* Wv = (const float*)d_in[5];
    const float* bv = (const float*)d_in[6];
    const float* Wo = (const float*)d_in[7];
    const float* bo = (const float*)d_in[8];
    const float* g1 = (const float*)d_in[9];
    const float* b1 = (const float*)d_in[10];
    const float* W1 = (const float*)d_in[11];
    const float* c1 = (const float*)d_in[12];
    const float* W2 = (const float*)d_in[13];
    const float* c2 = (const float*)d_in[14];
    const float* g2 = (const float*)d_in[15];
    const float* b2 = (const float*)d_in[16];
    float* out = (float*)d_out;

    float *pX1, *pF, *pbqkv;
    __half *pAh, *pHh, *pBq, *pBo, *pB1, *pB2;
    cudaGetSymbolAddress((void**)&pX1,  g_X1);
    cudaGetSymbolAddress((void**)&pF,   g_F);
    cudaGetSymbolAddress((void**)&pbqkv,g_bqkv);
    cudaGetSymbolAddress((void**)&pAh,  g_Ah);
    cudaGetSymbolAddress((void**)&pHh,  g_Hh);
    cudaGetSymbolAddress((void**)&pBq,  g_Bq);
    cudaGetSymbolAddress((void**)&pBo,  g_Bo);
    cudaGetSymbolAddress((void**)&pB1,  g_B1);
    cudaGetSymbolAddress((void**)&pB2,  g_B2);

    cudaFuncSetAttribute(attn_kernel, cudaFuncAttributeMaxDynamicSharedMemorySize, ATTN_SMEM);
    cudaFuncSetAttribute(gemm_tc_kernel, cudaFuncAttributeMaxDynamicSharedMemorySize, G_SMEM);

    dim3 blk(256);
    dim3 t32(32, 8);
    const int n4_1 = NTOK * HID / 4;
    dim3 gs1((n4_1 + 255) / 256);
    dim3 ggqkv(3 * HID / 128, NTOK / 128);
    dim3 gg1(HID / 128, NTOK / 128);
    dim3 gg4(4 * HID / 128, NTOK / 128);

    // ---- conversions: x, all weight transposes + bias pack in one launch ----
    cvt_kernel<<<gs1, blk>>>(x, pAh, n4_1);
    prep_kernel<<<12291, t32>>>(Wq, Wk, Wv, Wo, W1, W2, bq, bk, bv,
                                pBq, pBo, pB1, pB2, pbqkv);

    // ---- QKV GEMM (N=3072) -> fp16 ----
    gemm_tc_kernel<<<ggqkv, blk, G_SMEM>>>(pAh, pBq, pbqkv,
                                           nullptr, pHh,
                                           NTOK, 3 * HID, HID, 0);

    // ---- tensor-core attention; emits O fp16 ----
    attn_kernel<<<dim3(64, 4), 512, ATTN_SMEM>>>(pHh, pAh);

    // ---- output projection, residual + LN1 (emits X1 fp32 + fp16) ----
    gemm_tc_kernel<<<gg1, blk, G_SMEM>>>(pAh, pBo, bo,
                                         pF, nullptr,
                                         NTOK, HID, HID, 0);
    ln_kernel<<<NTOK, blk>>>(pF, x, g1, b1, pX1, pAh);

    // ---- FFN ----
    gemm_tc_kernel<<<gg4, blk, G_SMEM>>>(pAh, pB1, c1,
                                         nullptr, pHh,
                                         NTOK, 4 * HID, HID, 1);
    gemm_tc_kernel<<<gg1, blk, G_SMEM>>>(pHh, pB2, c2,
                                         pF, nullptr,
                                         NTOK, HID, 4 * HID, 0);

    // ---- residual + LN2 -> output ----
    ln_kernel<<<NTOK, blk>>>(pF, pX1, g2, b2, out, nullptr);
}

// round 13
// speedup vs baseline: 1.0620x; 1.0461x over previous
#include <cuda_runtime.h>
#include <cuda_fp16.h>
#include <stdint.h>
#include <math.h>

// ---------------- scratch buffers (static device memory, no allocs) ----------
#define NTOK 4096              // 4 * 1024 rows
#define HID  1024
__device__ float g_X1 [NTOK * HID];
__device__ float g_F  [NTOK * HID];
__device__ float g_bqkv[3 * HID];
__device__ __half g_Ah[NTOK * HID];       // activations fp16 (x / O / X1)
__device__ __half g_Hh[NTOK * 4 * HID];   // QKV, later FF hidden
__device__ __half g_Bq[3 * HID * HID];    // W_{q,k,v}^T fp16
__device__ __half g_Bo[HID * HID];        // Wo^T
__device__ __half g_B1[4 * HID * HID];    // W1^T
__device__ __half g_B2[4 * HID * HID];    // W2^T

// ---------------- PTX helpers (arch-neutral only) -----------------------------
__device__ __forceinline__ uint32_t smem_u32(const void* p) {
    uint32_t a;
    asm("{ .reg .u64 t; cvta.to.shared.u64 t, %1; cvt.u32.u64 %0, t; }"
        : "=r"(a) : "l"(p));
    return a;
}
#define CP_ASYNC16(s, g) \
    asm volatile("cp.async.cg.shared.global [%0], [%1], 16;" :: "r"(s), "l"(g))
#define CP_COMMIT() asm volatile("cp.async.commit_group;" ::: "memory")
#define CP_WAIT(n)  asm volatile("cp.async.wait_group %0;" :: "n"(n) : "memory")
#define LDSM_X4(r, addr) \
    asm volatile("ldmatrix.sync.aligned.m8n8.x4.shared.b16 {%0,%1,%2,%3}, [%4];" \
        : "=r"((r)[0]), "=r"((r)[1]), "=r"((r)[2]), "=r"((r)[3]) : "r"(addr))
#define LDSM_X2(r, addr) \
    asm volatile("ldmatrix.sync.aligned.m8n8.x2.shared.b16 {%0,%1}, [%2];" \
        : "=r"((r)[0]), "=r"((r)[1]) : "r"(addr))
#define LDSM_X2T(r, addr) \
    asm volatile("ldmatrix.sync.aligned.m8n8.x2.trans.shared.b16 {%0,%1}, [%2];" \
        : "=r"((r)[0]), "=r"((r)[1]) : "r"(addr))
#define MMAF16(c, a, b0, b1) \
    asm volatile("mma.sync.aligned.m16n8k16.row.col.f32.f16.f16.f32 " \
        "{%0,%1,%2,%3}, {%4,%5,%6,%7}, {%8,%9}, {%0,%1,%2,%3};" \
        : "+f"((c)[0]), "+f"((c)[1]), "+f"((c)[2]), "+f"((c)[3]) \
        : "r"((a)[0]), "r"((a)[1]), "r"((a)[2]), "r"((a)[3]), "r"(b0), "r"(b1))

__device__ __forceinline__ uint32_t pack_h2f(float x, float y) {
    __half2 p = __halves2half2(__float2half_rn(x), __float2half_rn(y));
    return *reinterpret_cast<uint32_t*>(&p);
}

// ---------------- conversion kernels -----------------------------------------
// fp32 -> fp16
__global__ __launch_bounds__(256) void cvt_kernel(
    const float* __restrict__ A, __half* __restrict__ H, int n4)
{
    int i = blockIdx.x * 256 + threadIdx.x;
    if (i >= n4) return;
    float4 v = ((const float4*)A)[i];
    ((__half2*)H)[i * 2 + 0] = __halves2half2(__float2half_rn(v.x), __float2half_rn(v.y));
    ((__half2*)H)[i * 2 + 1] = __halves2half2(__float2half_rn(v.z), __float2half_rn(v.w));
}

// transpose+round one 32x32 tile of W [K x N] fp32 -> H [N x K] fp16
__device__ __forceinline__ void tsplit_tile(
    const float* __restrict__ W, __half* __restrict__ H,
    int K, int N, int bk, int bn, float (*t)[33])
{
    const int tx = threadIdx.x, ty = threadIdx.y;
    #pragma unroll
    for (int j = 0; j < 4; ++j)
        t[ty + j * 8][tx] = W[(size_t)(bk + ty + j * 8) * N + bn + tx];
    __syncthreads();
    #pragma unroll
    for (int j = 0; j < 4; ++j) {
        int r = ty + j * 8;
        H[(size_t)(bn + r) * K + bk + tx] = __float2half_rn(t[tx][r]);
    }
}

// one launch: all weight transposes + QKV bias packing
__global__ __launch_bounds__(256) void prep_kernel(
    const float* __restrict__ Wq, const float* __restrict__ Wk,
    const float* __restrict__ Wv, const float* __restrict__ Wo,
    const float* __restrict__ W1, const float* __restrict__ W2,
    const float* __restrict__ bq, const float* __restrict__ bk,
    const float* __restrict__ bv,
    __half* __restrict__ Hq, __half* __restrict__ Ho,
    __half* __restrict__ H1, __half* __restrict__ H2,
    float* __restrict__ bqkv)
{
    __shared__ float t[32][33];
    int id = blockIdx.x;
    if (id < 3072) {                        // Wq|Wk|Wv: 3 x 1024 tiles
        int z = id >> 10, i2 = id & 1023;
        const float* W = (z == 0) ? Wq : (z == 1) ? Wk : Wv;
        tsplit_tile(W, Hq + (size_t)z * HID * HID, HID, HID,
                    (i2 >> 5) * 32, (i2 & 31) * 32, t);
    } else if (id < 4096) {                 // Wo
        int i2 = id - 3072;
        tsplit_tile(Wo, Ho, HID, HID, (i2 >> 5) * 32, (i2 & 31) * 32, t);
    } else if (id < 8192) {                 // W1: K=1024, N=4096
        int i2 = id - 4096;
        tsplit_tile(W1, H1, HID, 4 * HID, (i2 >> 7) * 32, (i2 & 127) * 32, t);
    } else if (id < 12288) {                // W2: K=4096, N=1024
        int i2 = id - 8192;
        tsplit_tile(W2, H2, 4 * HID, HID, (i2 >> 5) * 32, (i2 & 31) * 32, t);
    } else {                                // bias pack: ids 12288..12290
        int z = id - 12288;
        const float* b = (z == 0) ? bq : (z == 1) ? bk : bv;
        int tid = threadIdx.y * 32 + threadIdx.x;
        #pragma unroll
        for (int j = 0; j < 4; ++j)
            bqkv[z * 1024 + tid + j * 256] = b[tid + j * 256];
    }
}

// ---------------- single-fp16 tensor-core GEMM (3-stage, 1 sync/k-tile) ------
// C = act(A @ B^T + bias); A [M,K] fp16, B [N,K] fp16, fp32 accum.
#define G_PART  8192
#define G_STAGE (2 * G_PART)     // 16 KB per stage
#define G_SMEM  (3 * G_STAGE)    // 48 KB ring

__global__ __launch_bounds__(256) void gemm_tc_kernel(
    const __half* __restrict__ Ah, const __half* __restrict__ Bh,
    const float* __restrict__ bias,
    float* __restrict__ Cf, __half* __restrict__ Ch,
    int M, int N, int K, int act)
{
    extern __shared__ char smem[];
    const uint32_t sb = smem_u32(smem);
    const int tid = threadIdx.x;
    const int wid = tid >> 5, lane = tid & 31;
    const int warp_m = wid >> 2, warp_n = wid & 3;
    const int bm = blockIdx.y * 128, bn = blockIdx.x * 128;

    float acc[4][4][4];
    #pragma unroll
    for (int i = 0; i < 4; ++i)
        #pragma unroll
        for (int j = 0; j < 4; ++j)
            #pragma unroll
            for (int r = 0; r < 4; ++r) acc[i][j][r] = 0.f;

    const int swz = (lane & 7) >> 1;
    const int rA = warp_m * 64 + ((lane >> 3) & 1) * 8 + (lane & 7);
    const int kA = lane >> 4;
    const int rB = warp_n * 32 + (lane >> 4) * 8 + (lane & 7);
    const int kB = (lane >> 3) & 1;

    const int nst = K >> 5;

    auto load_stage = [&](int j, int slot) {
        const uint32_t st = sb + (uint32_t)slot * G_STAGE;
        const int kc = j * 32;
        #pragma unroll
        for (int t = 0; t < 2; ++t) {
            int idx = tid + t * 256;
            int row = idx >> 2, ch = idx & 3;
            uint32_t so = (uint32_t)row * 64 + (uint32_t)((ch ^ ((row >> 1) & 3)) << 4);
            size_t ga = (size_t)(bm + row) * K + kc + ch * 8;
            size_t gb = (size_t)(bn + row) * K + kc + ch * 8;
            CP_ASYNC16(st + 0 * G_PART + so, Ah + ga);
            CP_ASYNC16(st + 1 * G_PART + so, Bh + gb);
        }
        CP_COMMIT();
    };

    load_stage(0, 0);
    load_stage(1, 1);

    int slot = 0, slot2 = 2;   // slot = j%3, slot2 = (j+2)%3
    for (int j = 0; j < nst; ++j) {
        if (j + 1 < nst) { CP_WAIT(1); }   // stage j complete
        else             { CP_WAIT(0); }
        __syncthreads();                    // everyone done with slot (j-1)%3 == slot2
        if (j + 2 < nst) load_stage(j + 2, slot2);

        const uint32_t st = sb + (uint32_t)slot * G_STAGE;
        #pragma unroll
        for (int ks = 0; ks < 2; ++ks) {
            uint32_t ah[4][4], bh[2][4];
            #pragma unroll
            for (int mt = 0; mt < 4; ++mt) {
                uint32_t ao = (uint32_t)(rA + mt * 16) * 64
                            + (uint32_t)(((ks * 2 + kA) ^ swz) << 4);
                LDSM_X4(ah[mt], st + 0 * G_PART + ao);
            }
            #pragma unroll
            for (int np = 0; np < 2; ++np) {
                uint32_t bo = (uint32_t)(rB + np * 16) * 64
                            + (uint32_t)(((ks * 2 + kB) ^ swz) << 4);
                LDSM_X4(bh[np], st + 1 * G_PART + bo);
            }
            #pragma unroll
            for (int mt = 0; mt < 4; ++mt)
                #pragma unroll
                for (int nt = 0; nt < 4; ++nt) {
                    const uint32_t* bhp = &bh[nt >> 1][(nt & 1) * 2];
                    MMAF16(acc[mt][nt], ah[mt], bhp[0], bhp[1]);
                }
        }
        slot  = (slot  == 2) ? 0 : slot  + 1;
        slot2 = (slot2 == 2) ? 0 : slot2 + 1;
    }

    // epilogue
    #pragma unroll
    for (int mt = 0; mt < 4; ++mt)
        #pragma unroll
        for (int nt = 0; nt < 4; ++nt) {
            int row0 = bm + warp_m * 64 + mt * 16 + (lane >> 2);
            int col  = bn + warp_n * 32 + nt * 8 + (lane & 3) * 2;
            float b0 = bias[col], b1 = bias[col + 1];
            float v[4];
            v[0] = acc[mt][nt][0] + b0;
            v[1] = acc[mt][nt][1] + b1;
            v[2] = acc[mt][nt][2] + b0;
            v[3] = acc[mt][nt][3] + b1;
            if (act) {
                #pragma unroll
                for (int r = 0; r < 4; ++r)
                    v[r] = 0.5f * v[r] * (1.f + erff(v[r] * 0.70710678118654752f));
            }
            if (Cf) {
                *(float2*)&Cf[(size_t)row0 * N + col]       = make_float2(v[0], v[1]);
                *(float2*)&Cf[(size_t)(row0 + 8) * N + col] = make_float2(v[2], v[3]);
            } else {
                uint32_t p0 = pack_h2f(v[0], v[1]);
                uint32_t p1 = pack_h2f(v[2], v[3]);
                *(uint32_t*)&Ch[(size_t)row0 * N + col]       = p0;
                *(uint32_t*)&Ch[(size_t)(row0 + 8) * N + col] = p1;
            }
        }
}

// ---------------- tensor-core attention (R10 structure, 1-pass softmax) -------
// QKV packed fp16 [4096][3072]. Per block (a, n): 16 warps, warp = head.
// CTA-wide staging, 2-slot double buffer, 3 syncs/iter. Softmax stores raw
// exp(s) plus per-(b,b') 1/sum; normalization folded into AV fragment build.
#define SCW(hh, b, p) ((hh) * 290 + (b) * 18 + (p))
#define AT_STG 65536                 // K (32KB) + V (32KB) per stage
#define ATTN_SMEM (2 * AT_STG + (290 * 16 + 288) * 4)

__global__ __launch_bounds__(512, 1) void attn_kernel(
    const __half* __restrict__ Ph, __half* __restrict__ Oh)
{
    extern __shared__ char smem[];
    const uint32_t sb = smem_u32(smem);
    float* sc   = (float*)(smem + 2 * AT_STG);
    float* invb = sc + 290 * 16;          // [16][18] padded 1/sum per (b, b')

    const int tid = threadIdx.x, lane = tid & 31, h = tid >> 5;
    const int a = blockIdx.x, n = blockIdx.y;
    const int lr = lane >> 2, lc = lane & 3;

    // ---- stage Q into stage-0 area, extract fragments ----
    {
        #pragma unroll
        for (int t = 0; t < 4; ++t) {
            int f = tid + t * 512;
            int hh = f >> 7, bp = (f >> 3) & 15, c = f & 7;
            uint32_t dst = (uint32_t)hh * 2048 + bp * 128 + ((c ^ (bp & 7)) << 4);
            size_t src = (size_t)(n * 1024 + hh * 64 + a) * 3072 + bp * 64 + c * 8;
            CP_ASYNC16(sb + dst, Ph + src);
        }
        CP_COMMIT(); CP_WAIT(0); __syncthreads();
    }
    uint32_t qh[4][4];
    {
        int b = lane & 15, cs = lane >> 4;
        #pragma unroll
        for (int ks = 0; ks < 4; ++ks) {
            uint32_t ad = (uint32_t)h * 2048 + b * 128
                        + (((ks * 2 + cs) ^ (b & 7)) << 4);
            LDSM_X4(qh[ks], sb + ad);
        }
    }
    __syncthreads();   // everyone done reading Q before KV overwrites stage 0

    auto stageKV = [&](int ap, int s) {
        uint32_t base = sb + (uint32_t)s * AT_STG;
        #pragma unroll
        for (int t = 0; t < 4; ++t) {
            int f = tid + t * 512;
            int hh = f >> 7, bp = (f >> 3) & 15, c = f & 7;
            uint32_t dst = (uint32_t)hh * 2048 + bp * 128 + ((c ^ (bp & 7)) << 4);
            size_t row = (size_t)(n * 1024 + hh * 64 + ap) * 3072;
            CP_ASYNC16(base + dst,         Ph + row + 1024 + bp * 64 + c * 8);
            CP_ASYNC16(base + 32768 + dst, Ph + row + 2048 + bp * 64 + c * 8);
        }
        CP_COMMIT();
    };

    float o[8][4];
    #pragma unroll
    for (int nt = 0; nt < 8; ++nt)
        #pragma unroll
        for (int r = 0; r < 4; ++r) o[nt][r] = 0.f;

    stageKV(0, 0);
    for (int ap = 0; ap < 64; ++ap) {
        const int s = ap & 1;
        CP_WAIT(0);        // stage(ap) complete (only group in flight)
        __syncthreads();   // syncA: also fences AV(ap-1) reads of sc & slot s^1

        const uint32_t kb = sb + (uint32_t)s * AT_STG;
        const uint32_t vb = kb + 32768;

        // ---- scores: S = Q K^T ----
        float sv[2][4];
        #pragma unroll
        for (int nt = 0; nt < 2; ++nt)
            #pragma unroll
            for (int r = 0; r < 4; ++r) sv[nt][r] = 0.f;
        {
            int bpr = lane & 7, khalf = (lane >> 3) & 1;
            #pragma unroll
            for (int ks = 0; ks < 4; ++ks)
                #pragma unroll
                for (int nt = 0; nt < 2; ++nt) {
                    int row = nt * 8 + bpr;
                    uint32_t ad = (uint32_t)h * 2048 + row * 128
                                + (((ks * 2 + khalf) ^ (row & 7)) << 4);
                    uint32_t k2[2];
                    LDSM_X2(k2, kb + ad);
                    MMAF16(sv[nt], qh[ks], k2[0], k2[1]);
                }
        }
        #pragma unroll
        for (int nt = 0; nt < 2; ++nt) {
            int c0 = nt * 8 + 2 * lc;
            sc[SCW(h, lr,     c0)]     = sv[nt][0] * 0.03125f;
            sc[SCW(h, lr,     c0 + 1)] = sv[nt][1] * 0.03125f;
            sc[SCW(h, lr + 8, c0)]     = sv[nt][2] * 0.03125f;
            sc[SCW(h, lr + 8, c0 + 1)] = sv[nt][3] * 0.03125f;
        }
        __syncthreads();   // syncB: sc complete; slot s^1 drained

        // prefetch next KV into slot s^1 (safe: last readers fenced above)
        if (ap + 1 < 64) stageKV(ap + 1, s ^ 1);

        // ---- 1-pass head-softmax: raw exp + 1/sum (no max: |s| < ~4) ----
        if (tid < 256) {
            const int pb = tid >> 4, pbp = tid & 15;
            float ssum = 0.f;
            #pragma unroll
            for (int hh = 0; hh < 16; ++hh) {
                float e = __expf(sc[SCW(hh, pb, pbp)]);
                ssum += e;
                sc[SCW(hh, pb, pbp)] = e;
            }
            invb[pb * 18 + pbp] = 1.f / ssum;
        }
        __syncthreads();   // syncC: exp values + inv ready

        // ---- W fragments: fp16(e * inv) ----
        uint32_t awh[4];
        {
            float i00 = invb[lr * 18 + 2 * lc],       i01 = invb[lr * 18 + 2 * lc + 1];
            float i10 = invb[(lr + 8) * 18 + 2 * lc], i11 = invb[(lr + 8) * 18 + 2 * lc + 1];
            float i02 = invb[lr * 18 + 2 * lc + 8],       i03 = invb[lr * 18 + 2 * lc + 9];
            float i12 = invb[(lr + 8) * 18 + 2 * lc + 8], i13 = invb[(lr + 8) * 18 + 2 * lc + 9];
            awh[0] = pack_h2f(sc[SCW(h, lr,     2 * lc)] * i00,
                              sc[SCW(h, lr,     2 * lc + 1)] * i01);
            awh[1] = pack_h2f(sc[SCW(h, lr + 8, 2 * lc)] * i10,
                              sc[SCW(h, lr + 8, 2 * lc + 1)] * i11);
            awh[2] = pack_h2f(sc[SCW(h, lr,     2 * lc + 8)] * i02,
                              sc[SCW(h, lr,     2 * lc + 9)] * i03);
            awh[3] = pack_h2f(sc[SCW(h, lr + 8, 2 * lc + 8)] * i12,
                              sc[SCW(h, lr + 8, 2 * lc + 9)] * i13);
        }

        // ---- AV: O += W V (V via ldmatrix.trans) ----
        {
            int bp = lane & 15;
            #pragma unroll
            for (int nt = 0; nt < 8; ++nt) {
                uint32_t ad = (uint32_t)h * 2048 + bp * 128
                            + ((nt ^ (bp & 7)) << 4);
                uint32_t v2[2];
                LDSM_X2T(v2, vb + ad);
                MMAF16(o[nt], awh, v2[0], v2[1]);
            }
        }
        // no end-of-loop barrier: next iter's syncA fences AV before overwrites
    }

    // ---- write O (one 1024-col row per head) as fp16 ----
    const size_t orow = (size_t)(n * 1024 + h * 64 + a) * 1024;
    #pragma unroll
    for (int nt = 0; nt < 8; ++nt) {
        int c0 = nt * 8 + 2 * lc;
        uint32_t p0 = pack_h2f(o[nt][0], o[nt][1]);
        uint32_t p1 = pack_h2f(o[nt][2], o[nt][3]);
        *(uint32_t*)(Oh + orow + lr * 64 + c0)       = p0;
        *(uint32_t*)(Oh + orow + (lr + 8) * 64 + c0) = p1;
    }
}

// ---------------- fused residual + LayerNorm (+ optional fp16 emit) ----------
__global__ __launch_bounds__(256) void ln_kernel(
    const float* __restrict__ A, const float* __restrict__ R,
    const float* __restrict__ g, const float* __restrict__ bta,
    float* __restrict__ out, __half* __restrict__ Xh)
{
    __shared__ float red[16];
    const int row = blockIdx.x;
    const int tid = threadIdx.x;

    float4 v = ((const float4*)(A + (size_t)row * 1024))[tid];
    float4 r = ((const float4*)(R + (size_t)row * 1024))[tid];
    v.x += r.x; v.y += r.y; v.z += r.z; v.w += r.w;

    float s  = v.x + v.y + v.z + v.w;
    float sq = v.x * v.x + v.y * v.y + v.z * v.z + v.w * v.w;
    #pragma unroll
    for (int o = 16; o > 0; o >>= 1) {
        s  += __shfl_xor_sync(0xffffffffu, s,  o);
        sq += __shfl_xor_sync(0xffffffffu, sq, o);
    }
    if ((tid & 31) == 0) { red[tid >> 5] = s; red[8 + (tid >> 5)] = sq; }
    __syncthreads();
    float S = 0.f, SQ = 0.f;
    #pragma unroll
    for (int w = 0; w < 8; ++w) { S += red[w]; SQ += red[8 + w]; }

    const float mean = S * (1.f / 1024.f);
    const float var  = SQ * (1.f / 1024.f) - mean * mean;
    const float rstd = rsqrtf(var + 1e-5f);

    float4 gv = ((const float4*)g)[tid];
    float4 bv = ((const float4*)bta)[tid];
    float4 o;
    o.x = (v.x - mean) * rstd * gv.x + bv.x;
    o.y = (v.y - mean) * rstd * gv.y + bv.y;
    o.z = (v.z - mean) * rstd * gv.z + bv.z;
    o.w = (v.w - mean) * rstd * gv.w + bv.w;
    ((float4*)(out + (size_t)row * 1024))[tid] = o;

    if (Xh) {
        size_t oo = (size_t)row * 1024 + tid * 4;
        *(__half2*)(Xh + oo)     = __halves2half2(__float2half_rn(o.x), __float2half_rn(o.y));
        *(__half2*)(Xh + oo + 2) = __halves2half2(__float2half_rn(o.z), __float2half_rn(o.w));
    }
}

// ---------------- launch ------------------------------------------------------
extern "C" void kernel_launch(void* const* d_in, const int* in_sizes, int n_in,
                              void* d_out, int out_size)
{
    const float* x  = (const float*)d_in[0];
    const float* Wq = (const float*)d_in[1];
    const float* bq = (const float*)d_in[2];
    const float* Wk = (const float*)d_in[3];
    const float* bk = (const float*)d_in[4];
    const float* Wv = (const float*)d_in[5];
    const float* bv = (const float*)d_in[6];
    const float* Wo = (const float*)d_in[7];
    const float* bo = (const float*)d_in[8];
    const float* g1 = (const float*)d_in[9];
    const float* b1 = (const float*)d_in[10];
    const float* W1 = (const float*)d_in[11];
    const float* c1 = (const float*)d_in[12];
    const float* W2 = (const float*)d_in[13];
    const float* c2 = (const float*)d_in[14];
    const float* g2 = (const float*)d_in[15];
    const float* b2 = (const float*)d_in[16];
    float* out = (float*)d_out;

    float *pX1, *pF, *pbqkv;
    __half *pAh, *pHh, *pBq, *pBo, *pB1, *pB2;
    cudaGetSymbolAddress((void**)&pX1,  g_X1);
    cudaGetSymbolAddress((void**)&pF,   g_F);
    cudaGetSymbolAddress((void**)&pbqkv,g_bqkv);
    cudaGetSymbolAddress((void**)&pAh,  g_Ah);
    cudaGetSymbolAddress((void**)&pHh,  g_Hh);
    cudaGetSymbolAddress((void**)&pBq,  g_Bq);
    cudaGetSymbolAddress((void**)&pBo,  g_Bo);
    cudaGetSymbolAddress((void**)&pB1,  g_B1);
    cudaGetSymbolAddress((void**)&pB2,  g_B2);

    cudaFuncSetAttribute(attn_kernel, cudaFuncAttributeMaxDynamicSharedMemorySize, ATTN_SMEM);
    cudaFuncSetAttribute(gemm_tc_kernel, cudaFuncAttributeMaxDynamicSharedMemorySize, G_SMEM);

    dim3 blk(256);
    dim3 t32(32, 8);
    const int n4_1 = NTOK * HID / 4;
    dim3 gs1((n4_1 + 255) / 256);
    dim3 ggqkv(3 * HID / 128, NTOK / 128);
    dim3 gg1(HID / 128, NTOK / 128);
    dim3 gg4(4 * HID / 128, NTOK / 128);

    // ---- conversions: x, all weight transposes + bias pack in one launch ----
    cvt_kernel<<<gs1, blk>>>(x, pAh, n4_1);
    prep_kernel<<<12291, t32>>>(Wq, Wk, Wv, Wo, W1, W2, bq, bk, bv,
                                pBq, pBo, pB1, pB2, pbqkv);

    // ---- QKV GEMM (N=3072) -> fp16 ----
    gemm_tc_kernel<<<ggqkv, blk, G_SMEM>>>(pAh, pBq, pbqkv,
                                           nullptr, pHh,
                                           NTOK, 3 * HID, HID, 0);

    // ---- tensor-core attention; emits O fp16 ----
    attn_kernel<<<dim3(64, 4), 512, ATTN_SMEM>>>(pHh, pAh);

    // ---- output projection, residual + LN1 (emits X1 fp32 + fp16) ----
    gemm_tc_kernel<<<gg1, blk, G_SMEM>>>(pAh, pBo, bo,
                                         pF, nullptr,
                                         NTOK, HID, HID, 0);
    ln_kernel<<<NTOK, blk>>>(pF, x, g1, b1, pX1, pAh);

    // ---- FFN ----
    gemm_tc_kernel<<<gg4, blk, G_SMEM>>>(pAh, pB1, c1,
                                         nullptr, pHh,
                                         NTOK, 4 * HID, HID, 1);
    gemm_tc_kernel<<<gg1, blk, G_SMEM>>>(pHh, pB2, c2,
                                         pF, nullptr,
                                         NTOK, HID, 4 * HID, 0);

    // ---- residual + LN2 -> output ----
    ln_kernel<<<NTOK, blk>>>(pF, pX1, g2, b2, out, nullptr);
}

// round 15
// speedup vs baseline: 1.0654x; 1.0032x over previous
#include <cuda_runtime.h>
#include <cuda_fp16.h>
#include <stdint.h>
#include <math.h>

// ---------------- scratch buffers (static device memory, no allocs) ----------
#define NTOK 4096              // 4 * 1024 rows
#define HID  1024
__device__ float g_X1 [NTOK * HID];
__device__ float g_F  [NTOK * HID];
__device__ float g_bqkv[3 * HID];
__device__ __half g_Ah[NTOK * HID];       // activations fp16 (x / O / X1)
__device__ __half g_Hh[NTOK * 4 * HID];   // QKV, later FF hidden
__device__ __half g_Bq[HID * 3 * HID];    // [K=1024][N=3072] Wq|Wk|Wv (natural)
__device__ __half g_Bo[HID * HID];        // [1024][1024]
__device__ __half g_B1[HID * 4 * HID];    // [1024][4096]
__device__ __half g_B2[4 * HID * HID];    // [4096][1024]

// ---------------- PTX helpers (arch-neutral only) -----------------------------
__device__ __forceinline__ uint32_t smem_u32(const void* p) {
    uint32_t a;
    asm("{ .reg .u64 t; cvta.to.shared.u64 t, %1; cvt.u32.u64 %0, t; }"
        : "=r"(a) : "l"(p));
    return a;
}
#define CP_ASYNC16(s, g) \
    asm volatile("cp.async.cg.shared.global [%0], [%1], 16;" :: "r"(s), "l"(g))
#define CP_COMMIT() asm volatile("cp.async.commit_group;" ::: "memory")
#define CP_WAIT(n)  asm volatile("cp.async.wait_group %0;" :: "n"(n) : "memory")
#define LDSM_X4(r, addr) \
    asm volatile("ldmatrix.sync.aligned.m8n8.x4.shared.b16 {%0,%1,%2,%3}, [%4];" \
        : "=r"((r)[0]), "=r"((r)[1]), "=r"((r)[2]), "=r"((r)[3]) : "r"(addr))
#define LDSM_X2(r, addr) \
    asm volatile("ldmatrix.sync.aligned.m8n8.x2.shared.b16 {%0,%1}, [%2];" \
        : "=r"((r)[0]), "=r"((r)[1]) : "r"(addr))
#define LDSM_X2T(r, addr) \
    asm volatile("ldmatrix.sync.aligned.m8n8.x2.trans.shared.b16 {%0,%1}, [%2];" \
        : "=r"((r)[0]), "=r"((r)[1]) : "r"(addr))
#define MMAF16(c, a, b0, b1) \
    asm volatile("mma.sync.aligned.m16n8k16.row.col.f32.f16.f16.f32 " \
        "{%0,%1,%2,%3}, {%4,%5,%6,%7}, {%8,%9}, {%0,%1,%2,%3};" \
        : "+f"((c)[0]), "+f"((c)[1]), "+f"((c)[2]), "+f"((c)[3]) \
        : "r"((a)[0]), "r"((a)[1]), "r"((a)[2]), "r"((a)[3]), "r"(b0), "r"(b1))

__device__ __forceinline__ uint32_t pack_h2f(float x, float y) {
    __half2 p = __halves2half2(__float2half_rn(x), __float2half_rn(y));
    return *reinterpret_cast<uint32_t*>(&p);
}
__device__ __forceinline__ uint2 cvt4(float4 v) {
    uint2 o;
    o.x = pack_h2f(v.x, v.y);
    o.y = pack_h2f(v.z, v.w);
    return o;
}

// ---------------- conversion kernels -----------------------------------------
// fp32 -> fp16 (x)
__global__ __launch_bounds__(256) void cvt_kernel(
    const float* __restrict__ A, __half* __restrict__ H, int n4)
{
    int i = blockIdx.x * 256 + threadIdx.x;
    if (i >= n4) return;
    ((uint2*)H)[i] = cvt4(((const float4*)A)[i]);
}

// streaming prep: all weights fp32 -> fp16 in natural [K][N] layout, + bias pack
// regions (float4 units): QKV 786432 | Wo 262144 | W1 1048576 | W2 1048576 | bias 768
__global__ __launch_bounds__(256) void prep_kernel(
    const float* __restrict__ Wq, const float* __restrict__ Wk,
    const float* __restrict__ Wv, const float* __restrict__ Wo,
    const float* __restrict__ W1, const float* __restrict__ W2,
    const float* __restrict__ bq, const float* __restrict__ bk,
    const float* __restrict__ bv,
    __half* __restrict__ Hq, __half* __restrict__ Ho,
    __half* __restrict__ H1, __half* __restrict__ H2,
    float* __restrict__ bqkv)
{
    int i = blockIdx.x * 256 + threadIdx.x;
    if (i < 786432) {                       // Wq|Wk|Wv -> Hq [1024][3072]
        int z = i >> 18, rem = i & 262143;  // 262144 f4 per weight
        const float* W = (z == 0) ? Wq : (z == 1) ? Wk : Wv;
        int k = rem >> 8, n4 = rem & 255;   // 256 f4 per 1024-col row
        uint2 o = cvt4(((const float4*)W)[rem]);
        *(uint2*)(Hq + (size_t)k * 3072 + z * 1024 + n4 * 4) = o;
    } else if (i < 1048576) {               // Wo
        int rem = i - 786432;
        ((uint2*)Ho)[rem] = cvt4(((const float4*)Wo)[rem]);
    } else if (i < 2097152) {               // W1
        int rem = i - 1048576;
        ((uint2*)H1)[rem] = cvt4(((const float4*)W1)[rem]);
    } else if (i < 3145728) {               // W2
        int rem = i - 2097152;
        ((uint2*)H2)[rem] = cvt4(((const float4*)W2)[rem]);
    } else if (i < 3146496) {               // bias pack (768 f4)
        int rem = i - 3145728;
        int z = rem >> 8, j = rem & 255;
        const float* b = (z == 0) ? bq : (z == 1) ? bk : bv;
        ((float4*)bqkv)[z * 256 + j] = ((const float4*)b)[j];
    }
}

// ---------------- single-fp16 tensor-core GEMM (trans-B, 3-stage) ------------
// C = act(A @ B + bias); A [M,K] fp16 row-major, B [K,N] fp16 row-major
// (natural weight layout; B fragments via ldmatrix.trans). fp32 accum.
#define G_PART  8192
#define G_STAGE (2 * G_PART)     // A 8KB + B 8KB per stage
#define G_SMEM  (3 * G_STAGE)    // 48 KB ring

__global__ __launch_bounds__(256) void gemm_tc_kernel(
    const __half* __restrict__ Ah, const __half* __restrict__ Bh,
    const float* __restrict__ bias,
    float* __restrict__ Cf, __half* __restrict__ Ch,
    int M, int N, int K, int act)
{
    extern __shared__ char smem[];
    const uint32_t sb = smem_u32(smem);
    const int tid = threadIdx.x;
    const int wid = tid >> 5, lane = tid & 31;
    const int warp_m = wid >> 2, warp_n = wid & 3;
    const int bm = blockIdx.y * 128, bn = blockIdx.x * 128;

    float acc[4][4][4];
    #pragma unroll
    for (int i = 0; i < 4; ++i)
        #pragma unroll
        for (int j = 0; j < 4; ++j)
            #pragma unroll
            for (int r = 0; r < 4; ++r) acc[i][j][r] = 0.f;

    const int swz = (lane & 7) >> 1;
    const int rA = warp_m * 64 + ((lane >> 3) & 1) * 8 + (lane & 7);
    const int kA = lane >> 4;
    const int kB16 = lane & 15;

    const int nst = K >> 5;

    // A tile: 128 rows x 64 B (4 chunks); B tile: 32 k-rows x 256 B (16 chunks)
    auto load_stage = [&](int j, int slot) {
        const uint32_t st = sb + (uint32_t)slot * G_STAGE;
        const int kc = j * 32;
        #pragma unroll
        for (int t = 0; t < 2; ++t) {
            int idx = tid + t * 256;
            int row = idx >> 2, ch = idx & 3;
            uint32_t so = (uint32_t)row * 64 + (uint32_t)((ch ^ ((row >> 1) & 3)) << 4);
            CP_ASYNC16(st + so, Ah + (size_t)(bm + row) * K + kc + ch * 8);
        }
        #pragma unroll
        for (int t = 0; t < 2; ++t) {
            int idx = tid + t * 256;
            int row = idx >> 4, c = idx & 15;
            uint32_t so = (uint32_t)row * 256 + (uint32_t)((c ^ (row & 15)) << 4);
            CP_ASYNC16(st + G_PART + so, Bh + (size_t)(kc + row) * N + bn + c * 8);
        }
        CP_COMMIT();
    };

    load_stage(0, 0);
    load_stage(1, 1);

    int slot = 0, slot2 = 2;   // slot = j%3, slot2 = (j+2)%3
    for (int j = 0; j < nst; ++j) {
        if (j + 1 < nst) { CP_WAIT(1); }
        else             { CP_WAIT(0); }
        __syncthreads();                    // slot (j-1)%3 == slot2 drained
        if (j + 2 < nst) load_stage(j + 2, slot2);

        const uint32_t st = sb + (uint32_t)slot * G_STAGE;
        #pragma unroll
        for (int ks = 0; ks < 2; ++ks) {
            uint32_t ah[4][4], bh[4][2];
            #pragma unroll
            for (int mt = 0; mt < 4; ++mt) {
                uint32_t ao = (uint32_t)(rA + mt * 16) * 64
                            + (uint32_t)(((ks * 2 + kA) ^ swz) << 4);
                LDSM_X4(ah[mt], st + ao);
            }
            {
                int krow = ks * 16 + kB16;
                uint32_t brow = st + G_PART + (uint32_t)krow * 256;
                #pragma unroll
                for (int nf = 0; nf < 4; ++nf) {
                    uint32_t chunk = (uint32_t)((warp_n * 4 + nf) ^ (krow & 15));
                    LDSM_X2T(bh[nf], brow + (chunk << 4));
                }
            }
            #pragma unroll
            for (int mt = 0; mt < 4; ++mt)
                #pragma unroll
                for (int nt = 0; nt < 4; ++nt)
                    MMAF16(acc[mt][nt], ah[mt], bh[nt][0], bh[nt][1]);
        }
        slot  = (slot  == 2) ? 0 : slot  + 1;
        slot2 = (slot2 == 2) ? 0 : slot2 + 1;
    }

    // epilogue
    #pragma unroll
    for (int mt = 0; mt < 4; ++mt)
        #pragma unroll
        for (int nt = 0; nt < 4; ++nt) {
            int row0 = bm + warp_m * 64 + mt * 16 + (lane >> 2);
            int col  = bn + warp_n * 32 + nt * 8 + (lane & 3) * 2;
            float b0 = bias[col], b1 = bias[col + 1];
            float v[4];
            v[0] = acc[mt][nt][0] + b0;
            v[1] = acc[mt][nt][1] + b1;
            v[2] = acc[mt][nt][2] + b0;
            v[3] = acc[mt][nt][3] + b1;
            if (act) {
                #pragma unroll
                for (int r = 0; r < 4; ++r)
                    v[r] = 0.5f * v[r] * (1.f + erff(v[r] * 0.70710678118654752f));
            }
            if (Cf) {
                *(float2*)&Cf[(size_t)row0 * N + col]       = make_float2(v[0], v[1]);
                *(float2*)&Cf[(size_t)(row0 + 8) * N + col] = make_float2(v[2], v[3]);
            } else {
                uint32_t p0 = pack_h2f(v[0], v[1]);
                uint32_t p1 = pack_h2f(v[2], v[3]);
                *(uint32_t*)&Ch[(size_t)row0 * N + col]       = p0;
                *(uint32_t*)&Ch[(size_t)(row0 + 8) * N + col] = p1;
            }
        }
}

// ---------------- tensor-core attention (R13 best: 1-pass softmax) ------------
#define SCW(hh, b, p) ((hh) * 290 + (b) * 18 + (p))
#define AT_STG 65536                 // K (32KB) + V (32KB) per stage
#define ATTN_SMEM (2 * AT_STG + (290 * 16 + 288) * 4)

__global__ __launch_bounds__(512, 1) void attn_kernel(
    const __half* __restrict__ Ph, __half* __restrict__ Oh)
{
    extern __shared__ char smem[];
    const uint32_t sb = smem_u32(smem);
    float* sc   = (float*)(smem + 2 * AT_STG);
    float* invb = sc + 290 * 16;          // [16][18] padded 1/sum per (b, b')

    const int tid = threadIdx.x, lane = tid & 31, h = tid >> 5;
    const int a = blockIdx.x, n = blockIdx.y;
    const int lr = lane >> 2, lc = lane & 3;

    // ---- stage Q into stage-0 area, extract fragments ----
    {
        #pragma unroll
        for (int t = 0; t < 4; ++t) {
            int f = tid + t * 512;
            int hh = f >> 7, bp = (f >> 3) & 15, c = f & 7;
            uint32_t dst = (uint32_t)hh * 2048 + bp * 128 + ((c ^ (bp & 7)) << 4);
            size_t src = (size_t)(n * 1024 + hh * 64 + a) * 3072 + bp * 64 + c * 8;
            CP_ASYNC16(sb + dst, Ph + src);
        }
        CP_COMMIT(); CP_WAIT(0); __syncthreads();
    }
    uint32_t qh[4][4];
    {
        int b = lane & 15, cs = lane >> 4;
        #pragma unroll
        for (int ks = 0; ks < 4; ++ks) {
            uint32_t ad = (uint32_t)h * 2048 + b * 128
                        + (((ks * 2 + cs) ^ (b & 7)) << 4);
            LDSM_X4(qh[ks], sb + ad);
        }
    }
    __syncthreads();   // everyone done reading Q before KV overwrites stage 0

    auto stageKV = [&](int ap, int s) {
        uint32_t base = sb + (uint32_t)s * AT_STG;
        #pragma unroll
        for (int t = 0; t < 4; ++t) {
            int f = tid + t * 512;
            int hh = f >> 7, bp = (f >> 3) & 15, c = f & 7;
            uint32_t dst = (uint32_t)hh * 2048 + bp * 128 + ((c ^ (bp & 7)) << 4);
            size_t row = (size_t)(n * 1024 + hh * 64 + ap) * 3072;
            CP_ASYNC16(base + dst,         Ph + row + 1024 + bp * 64 + c * 8);
            CP_ASYNC16(base + 32768 + dst, Ph + row + 2048 + bp * 64 + c * 8);
        }
        CP_COMMIT();
    };

    float o[8][4];
    #pragma unroll
    for (int nt = 0; nt < 8; ++nt)
        #pragma unroll
        for (int r = 0; r < 4; ++r) o[nt][r] = 0.f;

    stageKV(0, 0);
    for (int ap = 0; ap < 64; ++ap) {
        const int s = ap & 1;
        CP_WAIT(0);
        __syncthreads();   // syncA

        const uint32_t kb = sb + (uint32_t)s * AT_STG;
        const uint32_t vb = kb + 32768;

        // ---- scores: S = Q K^T ----
        float sv[2][4];
        #pragma unroll
        for (int nt = 0; nt < 2; ++nt)
            #pragma unroll
            for (int r = 0; r < 4; ++r) sv[nt][r] = 0.f;
        {
            int bpr = lane & 7, khalf = (lane >> 3) & 1;
            #pragma unroll
            for (int ks = 0; ks < 4; ++ks)
                #pragma unroll
                for (int nt = 0; nt < 2; ++nt) {
                    int row = nt * 8 + bpr;
                    uint32_t ad = (uint32_t)h * 2048 + row * 128
                                + (((ks * 2 + khalf) ^ (row & 7)) << 4);
                    uint32_t k2[2];
                    LDSM_X2(k2, kb + ad);
                    MMAF16(sv[nt], qh[ks], k2[0], k2[1]);
                }
        }
        #pragma unroll
        for (int nt = 0; nt < 2; ++nt) {
            int c0 = nt * 8 + 2 * lc;
            sc[SCW(h, lr,     c0)]     = sv[nt][0] * 0.03125f;
            sc[SCW(h, lr,     c0 + 1)] = sv[nt][1] * 0.03125f;
            sc[SCW(h, lr + 8, c0)]     = sv[nt][2] * 0.03125f;
            sc[SCW(h, lr + 8, c0 + 1)] = sv[nt][3] * 0.03125f;
        }
        __syncthreads();   // syncB

        if (ap + 1 < 64) stageKV(ap + 1, s ^ 1);

        // ---- 1-pass head-softmax: raw exp + 1/sum ----
        if (tid < 256) {
            const int pb = tid >> 4, pbp = tid & 15;
            float ssum = 0.f;
            #pragma unroll
            for (int hh = 0; hh < 16; ++hh) {
                float e = __expf(sc[SCW(hh, pb, pbp)]);
                ssum += e;
                sc[SCW(hh, pb, pbp)] = e;
            }
            invb[pb * 18 + pbp] = 1.f / ssum;
        }
        __syncthreads();   // syncC

        // ---- W fragments: fp16(e * inv) ----
        uint32_t awh[4];
        {
            float i00 = invb[lr * 18 + 2 * lc],       i01 = invb[lr * 18 + 2 * lc + 1];
            float i10 = invb[(lr + 8) * 18 + 2 * lc], i11 = invb[(lr + 8) * 18 + 2 * lc + 1];
            float i02 = invb[lr * 18 + 2 * lc + 8],       i03 = invb[lr * 18 + 2 * lc + 9];
            float i12 = invb[(lr + 8) * 18 + 2 * lc + 8], i13 = invb[(lr + 8) * 18 + 2 * lc + 9];
            awh[0] = pack_h2f(sc[SCW(h, lr,     2 * lc)] * i00,
                              sc[SCW(h, lr,     2 * lc + 1)] * i01);
            awh[1] = pack_h2f(sc[SCW(h, lr + 8, 2 * lc)] * i10,
                              sc[SCW(h, lr + 8, 2 * lc + 1)] * i11);
            awh[2] = pack_h2f(sc[SCW(h, lr,     2 * lc + 8)] * i02,
                              sc[SCW(h, lr,     2 * lc + 9)] * i03);
            awh[3] = pack_h2f(sc[SCW(h, lr + 8, 2 * lc + 8)] * i12,
                              sc[SCW(h, lr + 8, 2 * lc + 9)] * i13);
        }

        // ---- AV: O += W V ----
        {
            int bp = lane & 15;
            #pragma unroll
            for (int nt = 0; nt < 8; ++nt) {
                uint32_t ad = (uint32_t)h * 2048 + bp * 128
                            + ((nt ^ (bp & 7)) << 4);
                uint32_t v2[2];
                LDSM_X2T(v2, vb + ad);
                MMAF16(o[nt], awh, v2[0], v2[1]);
            }
        }
    }

    // ---- write O as fp16 ----
    const size_t orow = (size_t)(n * 1024 + h * 64 + a) * 1024;
    #pragma unroll
    for (int nt = 0; nt < 8; ++nt) {
        int c0 = nt * 8 + 2 * lc;
        uint32_t p0 = pack_h2f(o[nt][0], o[nt][1]);
        uint32_t p1 = pack_h2f(o[nt][2], o[nt][3]);
        *(uint32_t*)(Oh + orow + lr * 64 + c0)       = p0;
        *(uint32_t*)(Oh + orow + (lr + 8) * 64 + c0) = p1;
    }
}

// ---------------- fused residual + LayerNorm (+ optional fp16 emit) ----------
__global__ __launch_bounds__(256) void ln_kernel(
    const float* __restrict__ A, const float* __restrict__ R,
    const float* __restrict__ g, const float* __restrict__ bta,
    float* __restrict__ out, __half* __restrict__ Xh)
{
    __shared__ float red[16];
    const int row = blockIdx.x;
    const int tid = threadIdx.x;

    float4 v = ((const float4*)(A + (size_t)row * 1024))[tid];
    float4 r = ((const float4*)(R + (size_t)row * 1024))[tid];
    v.x += r.x; v.y += r.y; v.z += r.z; v.w += r.w;

    float s  = v.x + v.y + v.z + v.w;
    float sq = v.x * v.x + v.y * v.y + v.z * v.z + v.w * v.w;
    #pragma unroll
    for (int o = 16; o > 0; o >>= 1) {
        s  += __shfl_xor_sync(0xffffffffu, s,  o);
        sq += __shfl_xor_sync(0xffffffffu, sq, o);
    }
    if ((tid & 31) == 0) { red[tid >> 5] = s; red[8 + (tid >> 5)] = sq; }
    __syncthreads();
    float S = 0.f, SQ = 0.f;
    #pragma unroll
    for (int w = 0; w < 8; ++w) { S += red[w]; SQ += red[8 + w]; }

    const float mean = S * (1.f / 1024.f);
    const float var  = SQ * (1.f / 1024.f) - mean * mean;
    const float rstd = rsqrtf(var + 1e-5f);

    float4 gv = ((const float4*)g)[tid];
    float4 bv = ((const float4*)bta)[tid];
    float4 o;
    o.x = (v.x - mean) * rstd * gv.x + bv.x;
    o.y = (v.y - mean) * rstd * gv.y + bv.y;
    o.z = (v.z - mean) * rstd * gv.z + bv.z;
    o.w = (v.w - mean) * rstd * gv.w + bv.w;
    ((float4*)(out + (size_t)row * 1024))[tid] = o;

    if (Xh) {
        size_t oo = (size_t)row * 1024 + tid * 4;
        *(__half2*)(Xh + oo)     = __halves2half2(__float2half_rn(o.x), __float2half_rn(o.y));
        *(__half2*)(Xh + oo + 2) = __halves2half2(__float2half_rn(o.z), __float2half_rn(o.w));
    }
}

// ---------------- launch ------------------------------------------------------
extern "C" void kernel_launch(void* const* d_in, const int* in_sizes, int n_in,
                              void* d_out, int out_size)
{
    const float* x  = (const float*)d_in[0];
    const float* Wq = (const float*)d_in[1];
    const float* bq = (const float*)d_in[2];
    const float* Wk = (const float*)d_in[3];
    const float* bk = (const float*)d_in[4];
    const float* Wv = (const float*)d_in[5];
    const float* bv = (const float*)d_in[6];
    const float* Wo = (const float*)d_in[7];
    const float* bo = (const float*)d_in[8];
    const float* g1 = (const float*)d_in[9];
    const float* b1 = (const float*)d_in[10];
    const float* W1 = (const float*)d_in[11];
    const float* c1 = (const float*)d_in[12];
    const float* W2 = (const float*)d_in[13];
    const float* c2 = (const float*)d_in[14];
    const float* g2 = (const float*)d_in[15];
    const float* b2 = (const float*)d_in[16];
    float* out = (float*)d_out;

    float *pX1, *pF, *pbqkv;
    __half *pAh, *pHh, *pBq, *pBo, *pB1, *pB2;
    cudaGetSymbolAddress((void**)&pX1,  g_X1);
    cudaGetSymbolAddress((void**)&pF,   g_F);
    cudaGetSymbolAddress((void**)&pbqkv,g_bqkv);
    cudaGetSymbolAddress((void**)&pAh,  g_Ah);
    cudaGetSymbolAddress((void**)&pHh,  g_Hh);
    cudaGetSymbolAddress((void**)&pBq,  g_Bq);
    cudaGetSymbolAddress((void**)&pBo,  g_Bo);
    cudaGetSymbolAddress((void**)&pB1,  g_B1);
    cudaGetSymbolAddress((void**)&pB2,  g_B2);

    cudaFuncSetAttribute(attn_kernel, cudaFuncAttributeMaxDynamicSharedMemorySize, ATTN_SMEM);
    cudaFuncSetAttribute(gemm_tc_kernel, cudaFuncAttributeMaxDynamicSharedMemorySize, G_SMEM);

    dim3 blk(256);
    const int n4_1 = NTOK * HID / 4;
    dim3 gs1((n4_1 + 255) / 256);
    dim3 ggqkv(3 * HID / 128, NTOK / 128);
    dim3 gg1(HID / 128, NTOK / 128);
    dim3 gg4(4 * HID / 128, NTOK / 128);

    // ---- conversions: x + all weights (streaming, no transpose) ----
    cvt_kernel<<<gs1, blk>>>(x, pAh, n4_1);
    prep_kernel<<<(3146496 + 255) / 256, blk>>>(Wq, Wk, Wv, Wo, W1, W2,
                                                bq, bk, bv,
                                                pBq, pBo, pB1, pB2, pbqkv);

    // ---- QKV GEMM (N=3072) -> fp16 ----
    gemm_tc_kernel<<<ggqkv, blk, G_SMEM>>>(pAh, pBq, pbqkv,
                                           nullptr, pHh,
                                           NTOK, 3 * HID, HID, 0);

    // ---- tensor-core attention; emits O fp16 ----
    attn_kernel<<<dim3(64, 4), 512, ATTN_SMEM>>>(pHh, pAh);

    // ---- output projection, residual + LN1 (emits X1 fp32 + fp16) ----
    gemm_tc_kernel<<<gg1, blk, G_SMEM>>>(pAh, pBo, bo,
                                         pF, nullptr,
                                         NTOK, HID, HID, 0);
    ln_kernel<<<NTOK, blk>>>(pF, x, g1, b1, pX1, pAh);

    // ---- FFN ----
    gemm_tc_kernel<<<gg4, blk, G_SMEM>>>(pAh, pB1, c1,
                                         nullptr, pHh,
                                         NTOK, 4 * HID, HID, 1);
    gemm_tc_kernel<<<gg1, blk, G_SMEM>>>(pHh, pB2, c2,
                                         pF, nullptr,
                                         NTOK, HID, 4 * HID, 0);

    // ---- residual + LN2 -> output ----
    ln_kernel<<<NTOK, blk>>>(pF, pX1, g2, b2, out, nullptr);
}